// round 5
// baseline (speedup 1.0000x reference)
#include <cuda_runtime.h>

// ---------------------------------------------------------------------------
// Scratch (no allocation allowed -> __device__ globals)
// ---------------------------------------------------------------------------
static __device__ float g_s0[8*8*128*128];    // conv s0 out [8,8,128,128]
static __device__ float g_s1[8*16*64*64];     // [8,16,64,64]
static __device__ float g_s2[8*32*32*32];     // [8,32,32,32]
static __device__ float g_s3[8*64*16*16];     // [8,64,16,16]
static __device__ float g_l1[8*64*16*16];     // lw1 out
static __device__ float g_xl[8*64*16*16];     // lw2 out (local head)
static __device__ float g_c0[8*64*8*8];       // cw0 out
static __device__ float g_c1[8*64*4*4];       // cw1 out ([B,1024] flattened)
static __device__ float g_xg[8*64];           // fc3 out
static __device__ float g_bg[8*8*16*16];      // bilateral grid [B,8,16,16]

__device__ __forceinline__ float relu_(float x){ return fmaxf(x, 0.0f); }

// Gaussian(sigma=2), 17 taps, normalized. Compile-time literals -> FFMA-imm.
#define GW0  6.691630e-05f
#define GW1  4.363500e-04f
#define GW2  2.215960e-03f
#define GW3  8.764310e-03f
#define GW4  2.699596e-02f
#define GW5  6.475993e-02f
#define GW6  1.209875e-01f
#define GW7  1.760357e-01f
#define GW8  1.994747e-01f
static __device__ constexpr float GW[17] = {
    GW0, GW1, GW2, GW3, GW4, GW5, GW6, GW7, GW8,
    GW7, GW6, GW5, GW4, GW3, GW2, GW1, GW0
};

// ---------------------------------------------------------------------------
// s0: in = concat(nearest(lqs,256), evs) [8,18,256,256] -> conv3x3 s2 p1 relu
//     out [8,8,128,128]. Input is gathered on the fly (no materialization).
// ---------------------------------------------------------------------------
__global__ void s0_kernel(const float* __restrict__ lqs, const float* __restrict__ evs,
                          const float* __restrict__ wt,  const float* __restrict__ bias,
                          float* __restrict__ out)
{
    int idx = blockIdx.x * 256 + threadIdx.x;           // exactly 1,048,576 threads
    int ox = idx & 127; int t = idx >> 7;
    int oy = t & 127;   t >>= 7;
    int co = t & 7;     int b = t >> 3;
    float acc = bias[co];
    for (int ci = 0; ci < 18; ci++) {
        const float* wp = wt + (co*18 + ci)*9;
        #pragma unroll
        for (int ky = 0; ky < 3; ky++) {
            int iy = 2*oy + ky - 1;
            if ((unsigned)iy >= 256u) continue;
            #pragma unroll
            for (int kx = 0; kx < 3; kx++) {
                int ix = 2*ox + kx - 1;
                if ((unsigned)ix >= 256u) continue;
                float v;
                if (ci < 3)  v = lqs[(b*3 + ci)*1048576 + (iy*4)*1024 + ix*4];  // nearest: floor(i*1024/256)=4i
                else         v = evs[(b*15 + (ci-3))*65536 + iy*256 + ix];
                acc = fmaf(v, wp[ky*3 + kx], acc);
            }
        }
    }
    out[idx] = relu_(acc);
}

// ---------------------------------------------------------------------------
// Generic direct 3x3 conv (pad=1), one thread per output element.
// ---------------------------------------------------------------------------
__global__ void conv3x3_kernel(const float* __restrict__ in, const float* __restrict__ wt,
                               const float* __restrict__ bias, float* __restrict__ out,
                               int B, int Cin, int Hin, int Win,
                               int Cout, int Hout, int Wout, int stride, int doRelu)
{
    int idx = blockIdx.x * blockDim.x + threadIdx.x;
    int total = B * Cout * Hout * Wout;
    if (idx >= total) return;
    int ox = idx % Wout; int t = idx / Wout;
    int oy = t % Hout;   t /= Hout;
    int co = t % Cout;   int b = t / Cout;
    float acc = bias ? bias[co] : 0.0f;
    const float* wco = wt + co*Cin*9;
    for (int ci = 0; ci < Cin; ci++) {
        const float* ip = in + (b*Cin + ci)*Hin*Win;
        const float* wp = wco + ci*9;
        #pragma unroll
        for (int ky = 0; ky < 3; ky++) {
            int iy = oy*stride + ky - 1;
            if ((unsigned)iy >= (unsigned)Hin) continue;
            #pragma unroll
            for (int kx = 0; kx < 3; kx++) {
                int ix = ox*stride + kx - 1;
                if ((unsigned)ix >= (unsigned)Win) continue;
                acc = fmaf(ip[iy*Win + ix], wp[ky*3 + kx], acc);
            }
        }
    }
    if (doRelu) acc = relu_(acc);
    out[idx] = acc;
}

// ---------------------------------------------------------------------------
// Fused FC stack: [B,1024] -> relu FC 256 -> relu FC 128 -> FC 64. 1 block/batch.
// ---------------------------------------------------------------------------
__global__ void fc_all_kernel(const float* __restrict__ xin,
                              const float* __restrict__ fw1, const float* __restrict__ fb1,
                              const float* __restrict__ fw2, const float* __restrict__ fb2,
                              const float* __restrict__ fw3, const float* __restrict__ fb3,
                              float* __restrict__ xg)
{
    __shared__ float sx[1024];
    __shared__ float s1[256];
    __shared__ float s2[128];
    int b = blockIdx.x, tid = threadIdx.x;   // 256 threads
    for (int i = tid; i < 1024; i += 256) sx[i] = xin[b*1024 + i];
    __syncthreads();
    {
        float acc = fb1[tid];
        const float* w = fw1 + tid*1024;
        #pragma unroll 4
        for (int k = 0; k < 1024; k++) acc = fmaf(sx[k], w[k], acc);
        s1[tid] = relu_(acc);
    }
    __syncthreads();
    if (tid < 128) {
        float acc = fb2[tid];
        const float* w = fw2 + tid*256;
        #pragma unroll 4
        for (int k = 0; k < 256; k++) acc = fmaf(s1[k], w[k], acc);
        s2[tid] = relu_(acc);
    }
    __syncthreads();
    if (tid < 64) {
        float acc = fb3[tid];
        const float* w = fw3 + tid*128;
        #pragma unroll 4
        for (int k = 0; k < 128; k++) acc = fmaf(s2[k], w[k], acc);
        xg[b*64 + tid] = acc;
    }
}

// ---------------------------------------------------------------------------
// bg = conv1x1(relu(xg[b,c] + xl[b,c,y,x]), fuw) + fub  -> [B,8,16,16]
// ---------------------------------------------------------------------------
__global__ void bg_kernel(const float* __restrict__ xl, const float* __restrict__ xg,
                          const float* __restrict__ fuw, const float* __restrict__ fub,
                          float* __restrict__ bg)
{
    int b = blockIdx.x, p = threadIdx.x;   // 256 threads = 16x16 pixels
    __shared__ float sxg[64];
    __shared__ float sw[8*64];
    if (p < 64) sxg[p] = xg[b*64 + p];
    for (int i = p; i < 512; i += 256) sw[i] = fuw[i];
    __syncthreads();
    float acc[8];
    #pragma unroll
    for (int g = 0; g < 8; g++) acc[g] = fub[g];
    for (int c = 0; c < 64; c++) {
        float f = relu_(sxg[c] + xl[(b*64 + c)*256 + p]);
        #pragma unroll
        for (int g = 0; g < 8; g++) acc[g] = fmaf(sw[g*64 + c], f, acc[g]);
    }
    #pragma unroll
    for (int g = 0; g < 8; g++) bg[(b*8 + g)*256 + p] = acc[g];
}

// ---------------------------------------------------------------------------
// Fused highres kernel: Gaussian blur (separable, reflect pad) + 1x1 convs ->
// guide -> trilinear slice of bilateral grid. One 32x32 output tile per block.
// ---------------------------------------------------------------------------
__device__ __forceinline__ int reflect1024(int i) {
    return i < 0 ? -i : (i > 1023 ? 2046 - i : i);
}

__global__ __launch_bounds__(1024)
void highres_kernel(const float* __restrict__ lqs,
                    const float* __restrict__ gw1, const float* __restrict__ gb1,
                    const float* __restrict__ gw2, const float* __restrict__ gb2,
                    const float* __restrict__ bg,  float* __restrict__ out)
{
    __shared__ float sIn[3][48][48];   // input tile + 8px halo, 27648 B
    __shared__ float sMid[3][48][32];  // h-blurred, 18432 B
    __shared__ float sW[81];           // gw1[48] | gb1[16] | gw2[16] | gb2[1]

    int tx = threadIdx.x, ty = threadIdx.y;
    int tid = ty*32 + tx;
    int bx = blockIdx.x*32, by = blockIdx.y*32, b = blockIdx.z;

    if (tid < 48)       sW[tid] = gw1[tid];
    else if (tid < 64)  sW[tid] = gb1[tid - 48];
    else if (tid < 80)  sW[tid] = gw2[tid - 64];
    else if (tid == 80) sW[80]  = gb2[0];

    const float* base = lqs + b*3*1048576;

    // Load 3x48x48 with reflect padding
    for (int i = tid; i < 3*48*48; i += 1024) {
        int ch = i / 2304; int rem = i - ch*2304;
        int r = rem / 48;  int c  = rem - r*48;
        int gy = reflect1024(by + r - 8);
        int gx = reflect1024(bx + c - 8);
        sIn[ch][r][c] = base[ch*1048576 + gy*1024 + gx];
    }
    __syncthreads();

    // Horizontal blur: 3x48x32 (taps are literals -> FFMA-imm)
    for (int i = tid; i < 3*48*32; i += 1024) {
        int ch = i / 1536; int rem = i - ch*1536;
        int r = rem / 32;  int c  = rem - r*32;
        float acc = 0.0f;
        #pragma unroll
        for (int k = 0; k < 17; k++) acc = fmaf(GW[k], sIn[ch][r][c + k], acc);
        sMid[ch][r][c] = acc;
    }
    __syncthreads();

    // Vertical blur for this thread's pixel
    float g0 = 0.0f, g1 = 0.0f, g2 = 0.0f;
    #pragma unroll
    for (int k = 0; k < 17; k++) {
        g0 = fmaf(GW[k], sMid[0][ty + k][tx], g0);
        g1 = fmaf(GW[k], sMid[1][ty + k][tx], g1);
        g2 = fmaf(GW[k], sMid[2][ty + k][tx], g2);
    }

    // 1x1 convs: 3 -> 16 relu -> 1, sigmoid, guide
    float s = sW[80];
    #pragma unroll
    for (int o = 0; o < 16; o++) {
        float h = fmaf(sW[o*3], g0, fmaf(sW[o*3+1], g1, fmaf(sW[o*3+2], g2, sW[48+o])));
        h = relu_(h);
        s = fmaf(sW[64+o], h, s);
    }
    float sig = 1.0f / (1.0f + __expf(-s));
    float guide = 2.0f*sig - 0.5f;

    // Slicing grid coordinates (match reference formulas exactly)
    int ox = bx + tx, oy = by + ty;
    float gxv = (ox + 0.5f) / 1024.0f * 2.0f - 0.5f;
    float gyv = (oy + 0.5f) / 1024.0f * 2.0f - 0.5f;
    float xs = fminf(fmaxf(((gxv + 1.0f)*16.0f - 1.0f)*0.5f, 0.0f), 15.0f);
    float ys = fminf(fmaxf(((gyv + 1.0f)*16.0f - 1.0f)*0.5f, 0.0f), 15.0f);
    float zs = fminf(fmaxf(((guide + 1.0f)*8.0f  - 1.0f)*0.5f, 0.0f), 7.0f);

    float x0f = floorf(xs), y0f = floorf(ys), z0f = floorf(zs);
    int x0 = (int)x0f, y0 = (int)y0f, z0 = (int)z0f;
    float fx = xs - x0f, fy = ys - y0f, fz = zs - z0f;
    int x1 = min(x0 + 1, 15), y1 = min(y0 + 1, 15), z1 = min(z0 + 1, 7);

    const float* bgb = bg + b*2048;   // [8,16,16], 64KB total -> L1/L2 resident
    float v000 = __ldg(&bgb[z0*256 + y0*16 + x0]);
    float v001 = __ldg(&bgb[z0*256 + y0*16 + x1]);
    float v010 = __ldg(&bgb[z0*256 + y1*16 + x0]);
    float v011 = __ldg(&bgb[z0*256 + y1*16 + x1]);
    float v100 = __ldg(&bgb[z1*256 + y0*16 + x0]);
    float v101 = __ldg(&bgb[z1*256 + y0*16 + x1]);
    float v110 = __ldg(&bgb[z1*256 + y1*16 + x0]);
    float v111 = __ldg(&bgb[z1*256 + y1*16 + x1]);

    float c00 = v000 + (v001 - v000)*fx;
    float c01 = v010 + (v011 - v010)*fx;
    float c10 = v100 + (v101 - v100)*fx;
    float c11 = v110 + (v111 - v110)*fx;
    float c0v = c00 + (c01 - c00)*fy;
    float c1v = c10 + (c11 - c10)*fy;
    float val = c0v + (c1v - c0v)*fz;

    out[b*1048576 + oy*1024 + ox] = val;
}

// ---------------------------------------------------------------------------
// kernel_launch
// ---------------------------------------------------------------------------
extern "C" void kernel_launch(void* const* d_in, const int* in_sizes, int n_in,
                              void* d_out, int out_size)
{
    const float* lqs = (const float*)d_in[0];
    const float* evs = (const float*)d_in[1];
    const float* gw1 = (const float*)d_in[2];
    const float* gb1 = (const float*)d_in[3];
    const float* gw2 = (const float*)d_in[4];
    const float* gb2 = (const float*)d_in[5];
    const float* sw0 = (const float*)d_in[6];
    const float* sb0 = (const float*)d_in[7];
    const float* sw1 = (const float*)d_in[8];
    const float* sb1 = (const float*)d_in[9];
    const float* sw2 = (const float*)d_in[10];
    const float* sb2 = (const float*)d_in[11];
    const float* sw3 = (const float*)d_in[12];
    const float* sb3 = (const float*)d_in[13];
    const float* cw0 = (const float*)d_in[14];
    const float* cb0 = (const float*)d_in[15];
    const float* cw1 = (const float*)d_in[16];
    const float* cb1 = (const float*)d_in[17];
    const float* fw1 = (const float*)d_in[18];
    const float* fb1 = (const float*)d_in[19];
    const float* fw2 = (const float*)d_in[20];
    const float* fb2 = (const float*)d_in[21];
    const float* fw3 = (const float*)d_in[22];
    const float* fb3 = (const float*)d_in[23];
    const float* lw1 = (const float*)d_in[24];
    const float* lb1 = (const float*)d_in[25];
    const float* lw2 = (const float*)d_in[26];
    const float* fuw = (const float*)d_in[27];
    const float* fub = (const float*)d_in[28];
    float* out = (float*)d_out;

    float *ps0, *ps1, *ps2, *ps3, *pl1, *pxl, *pc0, *pc1, *pxg, *pbg;
    cudaGetSymbolAddress((void**)&ps0, g_s0);
    cudaGetSymbolAddress((void**)&ps1, g_s1);
    cudaGetSymbolAddress((void**)&ps2, g_s2);
    cudaGetSymbolAddress((void**)&ps3, g_s3);
    cudaGetSymbolAddress((void**)&pl1, g_l1);
    cudaGetSymbolAddress((void**)&pxl, g_xl);
    cudaGetSymbolAddress((void**)&pc0, g_c0);
    cudaGetSymbolAddress((void**)&pc1, g_c1);
    cudaGetSymbolAddress((void**)&pxg, g_xg);
    cudaGetSymbolAddress((void**)&pbg, g_bg);

    // ---- lowres path ----
    s0_kernel<<<4096, 256>>>(lqs, evs, sw0, sb0, ps0);
    conv3x3_kernel<<<2048, 256>>>(ps0, sw1, sb1, ps1, 8, 8, 128, 128, 16, 64, 64, 2, 1);
    conv3x3_kernel<<<1024, 256>>>(ps1, sw2, sb2, ps2, 8, 16, 64, 64, 32, 32, 32, 2, 1);
    conv3x3_kernel<<<512, 256>>>(ps2, sw3, sb3, ps3, 8, 32, 32, 32, 64, 16, 16, 2, 1);
    // local head
    conv3x3_kernel<<<512, 256>>>(ps3, lw1, lb1, pl1, 8, 64, 16, 16, 64, 16, 16, 1, 1);
    conv3x3_kernel<<<512, 256>>>(pl1, lw2, (const float*)nullptr, pxl, 8, 64, 16, 16, 64, 16, 16, 1, 0);
    // global head
    conv3x3_kernel<<<128, 256>>>(ps3, cw0, cb0, pc0, 8, 64, 16, 16, 64, 8, 8, 2, 1);
    conv3x3_kernel<<<32, 256>>>(pc0, cw1, cb1, pc1, 8, 64, 8, 8, 64, 4, 4, 2, 1);
    fc_all_kernel<<<8, 256>>>(pc1, fw1, fb1, fw2, fb2, fw3, fb3, pxg);
    bg_kernel<<<8, 256>>>(pxl, pxg, fuw, fub, pbg);

    // ---- fused highres: blur + guide + slice ----
    highres_kernel<<<dim3(32, 32, 8), dim3(32, 32)>>>(lqs, gw1, gb1, gw2, gb2, pbg, out);
}

// round 9
// speedup vs baseline: 1.0656x; 1.0656x over previous
#include <cuda_runtime.h>

// ---------------------------------------------------------------------------
// Scratch (no allocation allowed -> __device__ globals)
// ---------------------------------------------------------------------------
static __device__ float g_s0[8*8*128*128];    // conv s0 out [8,8,128,128]
static __device__ float g_s1[8*16*64*64];     // [8,16,64,64]
static __device__ float g_s2[8*32*32*32];     // [8,32,32,32]
static __device__ float g_s3[8*64*16*16];     // [8,64,16,16]
static __device__ float g_l1[8*64*16*16];     // lw1 out
static __device__ float g_xl[8*64*16*16];     // lw2 out (local head)
static __device__ float g_c0[8*64*8*8];       // cw0 out
static __device__ float g_c1[8*64*4*4];       // cw1 out ([B,1024] flattened)
static __device__ float g_xg[8*64];           // fc3 out
static __device__ float g_bg[8*8*16*16];      // bilateral grid [B,8,16,16]

__device__ __forceinline__ float relu_(float x){ return fmaxf(x, 0.0f); }

// Gaussian(sigma=2), 17 taps, normalized. Compile-time literals -> FFMA-imm.
static __device__ constexpr float GW[17] = {
    6.691630e-05f, 4.363500e-04f, 2.215960e-03f, 8.764310e-03f,
    2.699596e-02f, 6.475993e-02f, 1.209875e-01f, 1.760357e-01f,
    1.994747e-01f,
    1.760357e-01f, 1.209875e-01f, 6.475993e-02f, 2.699596e-02f,
    8.764310e-03f, 2.215960e-03f, 4.363500e-04f, 6.691630e-05f
};

// ---------------------------------------------------------------------------
// Tiled conv3x3, pad=1. Block: (TILE/2)^2 x 4 threads. Each thread computes
// 2x2 output pixels x 4 output channels. 16 co per block. Input staged in
// smem in ci-chunks of CICH. Weights staged in smem (warp-broadcast reads).
// ---------------------------------------------------------------------------
template<int TILE, int STRIDE, int CICH, bool RELU, bool HASBIAS>
__global__ void conv_tile_kernel(const float* __restrict__ in, const float* __restrict__ wt,
                                 const float* __restrict__ bias, float* __restrict__ out,
                                 int Cin, int Hin, int Win,
                                 int Cout, int Hout, int Wout, int tilesX)
{
    constexpr int P  = TILE*STRIDE + 2;   // input patch size
    constexpr int WR = STRIDE + 3;        // per-thread input window
    constexpr int PXT = (TILE/2)*(TILE/2);
    __shared__ float sIn[CICH][P][P];
    __shared__ float sW[16][CICH][9];

    const int b    = blockIdx.z;
    const int co0  = blockIdx.y * 16;
    const int tileX = (blockIdx.x % tilesX) * TILE;
    const int tileY = (blockIdx.x / tilesX) * TILE;
    const int t   = threadIdx.x;          // 0..PXT-1
    const int cg  = threadIdx.y;          // 0..3
    const int tid = cg*PXT + t;
    const int nthr = PXT*4;
    const int txh = t % (TILE/2);
    const int tyh = t / (TILE/2);

    float acc[4][2][2];
    #pragma unroll
    for (int c = 0; c < 4; c++)
        #pragma unroll
        for (int dy = 0; dy < 2; dy++)
            #pragma unroll
            for (int dx = 0; dx < 2; dx++) acc[c][dy][dx] = 0.0f;

    const int iy0 = tileY*STRIDE - 1;
    const int ix0 = tileX*STRIDE - 1;
    const long inBase = (long)b * Cin * Hin * Win;

    for (int ci0 = 0; ci0 < Cin; ci0 += CICH) {
        // stage input patch
        for (int i = tid; i < CICH*P*P; i += nthr) {
            int ci = i / (P*P); int rem = i - ci*(P*P);
            int r = rem / P;    int c = rem - r*P;
            int iy = iy0 + r, ix = ix0 + c;
            float v = 0.0f;
            if ((unsigned)iy < (unsigned)Hin && (unsigned)ix < (unsigned)Win)
                v = in[inBase + (long)(ci0+ci)*Hin*Win + iy*Win + ix];
            sIn[ci][r][c] = v;
        }
        // stage weights
        for (int i = tid; i < 16*CICH*9; i += nthr) {
            int co = i / (CICH*9); int rem = i - co*(CICH*9);
            int ci = rem / 9;      int k = rem - ci*9;
            sW[co][ci][k] = wt[((co0+co)*Cin + (ci0+ci))*9 + k];
        }
        __syncthreads();

        const int ry = (tyh*2)*STRIDE;
        const int rx = (txh*2)*STRIDE;
        #pragma unroll
        for (int ci = 0; ci < CICH; ci++) {
            float win[WR][WR];
            #pragma unroll
            for (int wy = 0; wy < WR; wy++)
                #pragma unroll
                for (int wx = 0; wx < WR; wx++)
                    win[wy][wx] = sIn[ci][ry+wy][rx+wx];
            #pragma unroll
            for (int c = 0; c < 4; c++) {
                #pragma unroll
                for (int ky = 0; ky < 3; ky++)
                    #pragma unroll
                    for (int kx = 0; kx < 3; kx++) {
                        float w = sW[cg*4 + c][ci][ky*3 + kx];
                        #pragma unroll
                        for (int dy = 0; dy < 2; dy++)
                            #pragma unroll
                            for (int dx = 0; dx < 2; dx++)
                                acc[c][dy][dx] = fmaf(win[dy*STRIDE+ky][dx*STRIDE+kx], w, acc[c][dy][dx]);
                    }
            }
        }
        __syncthreads();
    }

    // store
    #pragma unroll
    for (int c = 0; c < 4; c++) {
        int co = co0 + cg*4 + c;
        float bv = HASBIAS ? bias[co] : 0.0f;
        #pragma unroll
        for (int dy = 0; dy < 2; dy++) {
            int oy = tileY + tyh*2 + dy;
            if (oy >= Hout) continue;
            #pragma unroll
            for (int dx = 0; dx < 2; dx++) {
                int ox = tileX + txh*2 + dx;
                if (ox >= Wout) continue;
                float v = acc[c][dy][dx] + bv;
                if (RELU) v = relu_(v);
                out[(((long)b*Cout + co)*Hout + oy)*Wout + ox] = v;
            }
        }
    }
}

// ---------------------------------------------------------------------------
// s0 tiled: in = concat(nearest(lqs,256), evs) [8,18,256,256] -> conv3x3 s2 p1
// relu -> [8,8,128,128]. Tile 16x16 out, 8 co, ci-chunks of 3.
// Block (64,2)=128 thr; grid (64,1,8).
// ---------------------------------------------------------------------------
__global__ void s0_tile_kernel(const float* __restrict__ lqs, const float* __restrict__ evs,
                               const float* __restrict__ wt,  const float* __restrict__ bias,
                               float* __restrict__ out)
{
    constexpr int P = 34;
    __shared__ float sIn[3][P][P];
    __shared__ float sW[8][3][9];

    const int b = blockIdx.z;
    const int tileX = (blockIdx.x % 8) * 16;
    const int tileY = (blockIdx.x / 8) * 16;
    const int t = threadIdx.x;     // 0..63
    const int cg = threadIdx.y;    // 0..1
    const int tid = cg*64 + t;
    const int txh = t % 8, tyh = t / 8;

    float acc[4][2][2];
    #pragma unroll
    for (int c = 0; c < 4; c++)
        #pragma unroll
        for (int dy = 0; dy < 2; dy++)
            #pragma unroll
            for (int dx = 0; dx < 2; dx++) acc[c][dy][dx] = 0.0f;

    const int iy0 = tileY*2 - 1;
    const int ix0 = tileX*2 - 1;

    for (int ci0 = 0; ci0 < 18; ci0 += 3) {
        for (int i = tid; i < 3*P*P; i += 128) {
            int ci = i / (P*P); int rem = i - ci*(P*P);
            int r = rem / P;    int c = rem - r*P;
            int iy = iy0 + r, ix = ix0 + c;
            float v = 0.0f;
            if ((unsigned)iy < 256u && (unsigned)ix < 256u) {
                int ch = ci0 + ci;
                if (ch < 3) v = lqs[(b*3 + ch)*1048576 + iy*4096 + ix*4];  // nearest: src=4*dst
                else        v = evs[(b*15 + (ch-3))*65536 + iy*256 + ix];
            }
            sIn[ci][r][c] = v;
        }
        for (int i = tid; i < 8*3*9; i += 128) {
            int co = i / 27; int rem = i - co*27;
            int ci = rem / 9; int k = rem - ci*9;
            sW[co][ci][k] = wt[(co*18 + (ci0+ci))*9 + k];
        }
        __syncthreads();

        const int ry = tyh*4;   // (tyh*2)*2
        const int rx = txh*4;
        #pragma unroll
        for (int ci = 0; ci < 3; ci++) {
            float win[5][5];
            #pragma unroll
            for (int wy = 0; wy < 5; wy++)
                #pragma unroll
                for (int wx = 0; wx < 5; wx++)
                    win[wy][wx] = sIn[ci][ry+wy][rx+wx];
            #pragma unroll
            for (int c = 0; c < 4; c++) {
                #pragma unroll
                for (int ky = 0; ky < 3; ky++)
                    #pragma unroll
                    for (int kx = 0; kx < 3; kx++) {
                        float w = sW[cg*4 + c][ci][ky*3 + kx];
                        #pragma unroll
                        for (int dy = 0; dy < 2; dy++)
                            #pragma unroll
                            for (int dx = 0; dx < 2; dx++)
                                acc[c][dy][dx] = fmaf(win[dy*2+ky][dx*2+kx], w, acc[c][dy][dx]);
                    }
            }
        }
        __syncthreads();
    }

    #pragma unroll
    for (int c = 0; c < 4; c++) {
        int co = cg*4 + c;
        float bv = bias[co];
        #pragma unroll
        for (int dy = 0; dy < 2; dy++) {
            int oy = tileY + tyh*2 + dy;
            #pragma unroll
            for (int dx = 0; dx < 2; dx++) {
                int ox = tileX + txh*2 + dx;
                out[((b*8 + co)*128 + oy)*128 + ox] = relu_(acc[c][dy][dx] + bv);
            }
        }
    }
}

// ---------------------------------------------------------------------------
// Fused FC stack: [B,1024] -> relu FC 256 -> relu FC 128 -> FC 64. 1 block/batch.
// ---------------------------------------------------------------------------
__global__ void fc_all_kernel(const float* __restrict__ xin,
                              const float* __restrict__ fw1, const float* __restrict__ fb1,
                              const float* __restrict__ fw2, const float* __restrict__ fb2,
                              const float* __restrict__ fw3, const float* __restrict__ fb3,
                              float* __restrict__ xg)
{
    __shared__ float sx[1024];
    __shared__ float s1[256];
    __shared__ float s2[128];
    int b = blockIdx.x, tid = threadIdx.x;   // 256 threads
    for (int i = tid; i < 1024; i += 256) sx[i] = xin[b*1024 + i];
    __syncthreads();
    {
        float acc = fb1[tid];
        const float* w = fw1 + tid*1024;
        #pragma unroll 4
        for (int k = 0; k < 1024; k++) acc = fmaf(sx[k], w[k], acc);
        s1[tid] = relu_(acc);
    }
    __syncthreads();
    if (tid < 128) {
        float acc = fb2[tid];
        const float* w = fw2 + tid*256;
        #pragma unroll 4
        for (int k = 0; k < 256; k++) acc = fmaf(s1[k], w[k], acc);
        s2[tid] = relu_(acc);
    }
    __syncthreads();
    if (tid < 64) {
        float acc = fb3[tid];
        const float* w = fw3 + tid*128;
        #pragma unroll 4
        for (int k = 0; k < 128; k++) acc = fmaf(s2[k], w[k], acc);
        xg[b*64 + tid] = acc;
    }
}

// ---------------------------------------------------------------------------
// bg = conv1x1(relu(xg[b,c] + xl[b,c,y,x]), fuw) + fub  -> [B,8,16,16]
// ---------------------------------------------------------------------------
__global__ void bg_kernel(const float* __restrict__ xl, const float* __restrict__ xg,
                          const float* __restrict__ fuw, const float* __restrict__ fub,
                          float* __restrict__ bg)
{
    int b = blockIdx.x, p = threadIdx.x;   // 256 threads = 16x16 pixels
    __shared__ float sxg[64];
    __shared__ float sw[8*64];
    if (p < 64) sxg[p] = xg[b*64 + p];
    for (int i = p; i < 512; i += 256) sw[i] = fuw[i];
    __syncthreads();
    float acc[8];
    #pragma unroll
    for (int g = 0; g < 8; g++) acc[g] = fub[g];
    for (int c = 0; c < 64; c++) {
        float f = relu_(sxg[c] + xl[(b*64 + c)*256 + p]);
        #pragma unroll
        for (int g = 0; g < 8; g++) acc[g] = fmaf(sw[g*64 + c], f, acc[g]);
    }
    #pragma unroll
    for (int g = 0; g < 8; g++) bg[(b*8 + g)*256 + p] = acc[g];
}

// ---------------------------------------------------------------------------
// Fused highres kernel: Gaussian blur (separable, reflect pad) + 1x1 convs ->
// guide -> trilinear slice of bilateral grid. 32x32 tile, 256 threads.
// Register sliding windows for both blur passes; smem padded conflict-free.
// ---------------------------------------------------------------------------
__device__ __forceinline__ int reflect1024(int i) {
    return i < 0 ? -i : (i > 1023 ? 2046 - i : i);
}

__global__ __launch_bounds__(256, 2)
void highres_kernel(const float* __restrict__ lqs,
                    const float* __restrict__ gw1, const float* __restrict__ gb1,
                    const float* __restrict__ gw2, const float* __restrict__ gb2,
                    const float* __restrict__ bg,  float* __restrict__ out)
{
    __shared__ float sIn[3][48][49];   // +1 pad col -> conflict-free window loads
    __shared__ float sMid[3][48][33];  // +1 pad col -> conflict-free stores/reads
    __shared__ float sW[81];           // gw1[48] | gb1[16] | gw2[16] | gb2[1]

    const int tid = threadIdx.x;       // 0..255
    const int bx = blockIdx.x*32, by = blockIdx.y*32, b = blockIdx.z;

    if (tid < 81)
        sW[tid] = (tid < 48) ? gw1[tid]
                : (tid < 64) ? gb1[tid - 48]
                : (tid < 80) ? gw2[tid - 64] : gb2[0];

    const float* base = lqs + b*3*1048576;

    // Load 3x48x48 with reflect padding
    for (int i = tid; i < 3*48*48; i += 256) {
        int ch = i / 2304; int rem = i - ch*2304;
        int r = rem / 48;  int c  = rem - r*48;
        sIn[ch][r][c] = base[ch*1048576 + reflect1024(by + r - 8)*1024 + reflect1024(bx + c - 8)];
    }
    __syncthreads();

    // Horizontal blur: 288 segments of 16 outputs, register sliding window.
    for (int s = tid; s < 288; s += 256) {
        int ch = s / 96; int rem = s - ch*96;
        int r = rem >> 1; int half = rem & 1;
        int c0 = half * 16;
        float w[32];
        #pragma unroll
        for (int j = 0; j < 32; j++) w[j] = sIn[ch][r][c0 + j];
        #pragma unroll
        for (int o = 0; o < 16; o++) {
            float a = 0.0f;
            #pragma unroll
            for (int k = 0; k < 17; k++) a = fmaf(GW[k], w[o + k], a);
            sMid[ch][r][c0 + o] = a;
        }
    }
    __syncthreads();

    // Vertical blur: each thread handles a column of 4 output rows.
    const int tx = tid & 31;
    const int qy = tid >> 5;           // 0..7
    float vb[3][4];
    #pragma unroll
    for (int ch = 0; ch < 3; ch++) {
        float col[20];
        #pragma unroll
        for (int k = 0; k < 20; k++) col[k] = sMid[ch][qy*4 + k][tx];
        #pragma unroll
        for (int d = 0; d < 4; d++) {
            float a = 0.0f;
            #pragma unroll
            for (int k = 0; k < 17; k++) a = fmaf(GW[k], col[d + k], a);
            vb[ch][d] = a;
        }
    }

    const float* bgb = bg + b*2048;    // [8,16,16], 64KB total -> L1/L2 resident
    const int ox = bx + tx;
    const float gxv = (ox + 0.5f) * (1.0f/1024.0f) * 2.0f - 0.5f;
    const float xs = fminf(fmaxf(((gxv + 1.0f)*16.0f - 1.0f)*0.5f, 0.0f), 15.0f);
    const float x0f = floorf(xs);
    const int x0 = (int)x0f;
    const float fx = xs - x0f;
    const int x1 = min(x0 + 1, 15);

    #pragma unroll
    for (int d = 0; d < 4; d++) {
        // 1x1 convs: 3 -> 16 relu -> 1, sigmoid, guide
        float ssum = sW[80];
        #pragma unroll
        for (int o = 0; o < 16; o++) {
            float h = fmaf(sW[o*3], vb[0][d], fmaf(sW[o*3+1], vb[1][d], fmaf(sW[o*3+2], vb[2][d], sW[48+o])));
            h = relu_(h);
            ssum = fmaf(sW[64+o], h, ssum);
        }
        float sig = 1.0f / (1.0f + __expf(-ssum));
        float guide = 2.0f*sig - 0.5f;

        int oy = by + qy*4 + d;
        float gyv = (oy + 0.5f) * (1.0f/1024.0f) * 2.0f - 0.5f;
        float ys = fminf(fmaxf(((gyv + 1.0f)*16.0f - 1.0f)*0.5f, 0.0f), 15.0f);
        float zs = fminf(fmaxf(((guide + 1.0f)*8.0f - 1.0f)*0.5f, 0.0f), 7.0f);

        float y0f = floorf(ys), z0f = floorf(zs);
        int y0 = (int)y0f, z0 = (int)z0f;
        float fy = ys - y0f, fz = zs - z0f;
        int y1 = min(y0 + 1, 15), z1 = min(z0 + 1, 7);

        float v000 = __ldg(&bgb[z0*256 + y0*16 + x0]);
        float v001 = __ldg(&bgb[z0*256 + y0*16 + x1]);
        float v010 = __ldg(&bgb[z0*256 + y1*16 + x0]);
        float v011 = __ldg(&bgb[z0*256 + y1*16 + x1]);
        float v100 = __ldg(&bgb[z1*256 + y0*16 + x0]);
        float v101 = __ldg(&bgb[z1*256 + y0*16 + x1]);
        float v110 = __ldg(&bgb[z1*256 + y1*16 + x0]);
        float v111 = __ldg(&bgb[z1*256 + y1*16 + x1]);

        float c00 = v000 + (v001 - v000)*fx;
        float c01 = v010 + (v011 - v010)*fx;
        float c10 = v100 + (v101 - v100)*fx;
        float c11 = v110 + (v111 - v110)*fx;
        float c0v = c00 + (c01 - c00)*fy;
        float c1v = c10 + (c11 - c10)*fy;
        float val = c0v + (c1v - c0v)*fz;

        out[b*1048576 + oy*1024 + ox] = val;
    }
}

// ---------------------------------------------------------------------------
// kernel_launch
// ---------------------------------------------------------------------------
extern "C" void kernel_launch(void* const* d_in, const int* in_sizes, int n_in,
                              void* d_out, int out_size)
{
    const float* lqs = (const float*)d_in[0];
    const float* evs = (const float*)d_in[1];
    const float* gw1 = (const float*)d_in[2];
    const float* gb1 = (const float*)d_in[3];
    const float* gw2 = (const float*)d_in[4];
    const float* gb2 = (const float*)d_in[5];
    const float* sw0 = (const float*)d_in[6];
    const float* sb0 = (const float*)d_in[7];
    const float* sw1 = (const float*)d_in[8];
    const float* sb1 = (const float*)d_in[9];
    const float* sw2 = (const float*)d_in[10];
    const float* sb2 = (const float*)d_in[11];
    const float* sw3 = (const float*)d_in[12];
    const float* sb3 = (const float*)d_in[13];
    const float* cw0 = (const float*)d_in[14];
    const float* cb0 = (const float*)d_in[15];
    const float* cw1 = (const float*)d_in[16];
    const float* cb1 = (const float*)d_in[17];
    const float* fw1 = (const float*)d_in[18];
    const float* fb1 = (const float*)d_in[19];
    const float* fw2 = (const float*)d_in[20];
    const float* fb2 = (const float*)d_in[21];
    const float* fw3 = (const float*)d_in[22];
    const float* fb3 = (const float*)d_in[23];
    const float* lw1 = (const float*)d_in[24];
    const float* lb1 = (const float*)d_in[25];
    const float* lw2 = (const float*)d_in[26];
    const float* fuw = (const float*)d_in[27];
    const float* fub = (const float*)d_in[28];
    float* out = (float*)d_out;

    float *ps0, *ps1, *ps2, *ps3, *pl1, *pxl, *pc0, *pc1, *pxg, *pbg;
    cudaGetSymbolAddress((void**)&ps0, g_s0);
    cudaGetSymbolAddress((void**)&ps1, g_s1);
    cudaGetSymbolAddress((void**)&ps2, g_s2);
    cudaGetSymbolAddress((void**)&ps3, g_s3);
    cudaGetSymbolAddress((void**)&pl1, g_l1);
    cudaGetSymbolAddress((void**)&pxl, g_xl);
    cudaGetSymbolAddress((void**)&pc0, g_c0);
    cudaGetSymbolAddress((void**)&pc1, g_c1);
    cudaGetSymbolAddress((void**)&pxg, g_xg);
    cudaGetSymbolAddress((void**)&pbg, g_bg);

    // ---- lowres path (all smem-tiled) ----
    s0_tile_kernel<<<dim3(64, 1, 8), dim3(64, 2)>>>(lqs, evs, sw0, sb0, ps0);
    conv_tile_kernel<16,2,4,true,true><<<dim3(16, 1, 8), dim3(64, 4)>>>(ps0, sw1, sb1, ps1, 8, 128, 128, 16, 64, 64, 4);
    conv_tile_kernel< 8,2,4,true,true><<<dim3(16, 2, 8), dim3(16, 4)>>>(ps1, sw2, sb2, ps2, 16, 64, 64, 32, 32, 32, 4);
    conv_tile_kernel< 8,2,4,true,true><<<dim3( 4, 4, 8), dim3(16, 4)>>>(ps2, sw3, sb3, ps3, 32, 32, 32, 64, 16, 16, 2);
    // local head
    conv_tile_kernel< 8,1,4,true,true ><<<dim3(4, 4, 8), dim3(16, 4)>>>(ps3, lw1, lb1, pl1, 64, 16, 16, 64, 16, 16, 2);
    conv_tile_kernel< 8,1,4,false,false><<<dim3(4, 4, 8), dim3(16, 4)>>>(pl1, lw2, (const float*)nullptr, pxl, 64, 16, 16, 64, 16, 16, 2);
    // global head
    conv_tile_kernel< 8,2,4,true,true><<<dim3(1, 4, 8), dim3(16, 4)>>>(ps3, cw0, cb0, pc0, 64, 16, 16, 64, 8, 8, 1);
    conv_tile_kernel< 8,2,4,true,true><<<dim3(1, 4, 8), dim3(16, 4)>>>(pc0, cw1, cb1, pc1, 64, 8, 8, 64, 4, 4, 1);
    fc_all_kernel<<<8, 256>>>(pc1, fw1, fb1, fw2, fb2, fw3, fb3, pxg);
    bg_kernel<<<8, 256>>>(pxl, pxg, fuw, fub, pbg);

    // ---- fused highres: blur + guide + slice ----
    highres_kernel<<<dim3(32, 32, 8), 256>>>(lqs, gw1, gb1, gw2, gb2, pbg, out);
}

// round 10
// speedup vs baseline: 1.0817x; 1.0151x over previous
#include <cuda_runtime.h>

// ---------------------------------------------------------------------------
// Scratch (no allocation allowed -> __device__ globals)
// ---------------------------------------------------------------------------
static __device__ float g_s0[8*8*128*128];    // conv s0 out [8,8,128,128]
static __device__ float g_s1[8*16*64*64];     // [8,16,64,64]
static __device__ float g_s2[8*32*32*32];     // [8,32,32,32]
static __device__ float g_s3[8*64*16*16];     // [8,64,16,16]
static __device__ float g_l1[8*64*16*16];     // lw1 out
static __device__ float g_xl[8*64*16*16];     // lw2 out (local head)
static __device__ float g_c0[8*64*8*8];       // cw0 out
static __device__ float g_xg[8*64];           // fc3 out
static __device__ float g_bg[8*8*16*16];      // bilateral grid [B,8,16,16]

__device__ __forceinline__ float relu_(float x){ return fmaxf(x, 0.0f); }

__device__ __forceinline__ float warp_sum(float v){
    #pragma unroll
    for (int o = 16; o > 0; o >>= 1) v += __shfl_down_sync(0xffffffffu, v, o);
    return v;
}

// Gaussian(sigma=2), 17 taps, normalized. Compile-time literals -> FFMA-imm.
static __device__ constexpr float GW[17] = {
    6.691630e-05f, 4.363500e-04f, 2.215960e-03f, 8.764310e-03f,
    2.699596e-02f, 6.475993e-02f, 1.209875e-01f, 1.760357e-01f,
    1.994747e-01f,
    1.760357e-01f, 1.209875e-01f, 6.475993e-02f, 2.699596e-02f,
    8.764310e-03f, 2.215960e-03f, 4.363500e-04f, 6.691630e-05f
};

// ---------------------------------------------------------------------------
// Stage-once conv3x3 (pad=1). Full input patch + all weights staged to dynamic
// smem once; compute with register row windows. Thread = (co group, out row),
// TX outputs per thread along x.
// ---------------------------------------------------------------------------
template<int CIN, int STRIDE, int COB, int CPT, int TY, int TX, bool RELU, bool HB>
__global__ void convf_kernel(const float* __restrict__ in, const float* __restrict__ wt,
                             const float* __restrict__ bias, float* __restrict__ out,
                             int HIN, int WIN, int Cout, int HOUT, int WOUT, int tilesX)
{
    constexpr int PH  = TY*STRIDE + 2;
    constexpr int PW  = TX*STRIDE + 2;
    constexpr int PWP = (PW % 2 == 0) ? PW + 1 : PW;   // odd -> conflict-free
    constexpr int NT  = (COB/CPT) * TY;
    constexpr int WR  = (TX-1)*STRIDE + 3;

    extern __shared__ float sm[];
    float* sIn = sm;                    // CIN*PH*PWP
    float* sW  = sm + CIN*PH*PWP;       // COB*CIN*9

    const int b   = blockIdx.z;
    const int co0 = blockIdx.y * COB;
    const int ox0 = (blockIdx.x % tilesX) * TX;
    const int oy0 = (blockIdx.x / tilesX) * TY;
    const int tid = threadIdx.x;

    const int iy0 = oy0*STRIDE - 1, ix0 = ox0*STRIDE - 1;
    for (int i = tid; i < CIN*PH*PW; i += NT) {
        int ci = i / (PH*PW); int rem = i - ci*(PH*PW);
        int r = rem / PW;     int c = rem - r*PW;
        int iy = iy0 + r, ix = ix0 + c;
        float v = 0.0f;
        if ((unsigned)iy < (unsigned)HIN && (unsigned)ix < (unsigned)WIN)
            v = in[((b*CIN + ci)*HIN + iy)*WIN + ix];
        sIn[(ci*PH + r)*PWP + c] = v;
    }
    for (int i = tid; i < COB*CIN*9; i += NT) {
        int co = i / (CIN*9); int rem = i - co*(CIN*9);
        sW[i] = wt[(co0 + co)*CIN*9 + rem];
    }
    __syncthreads();

    const int y  = tid % TY;
    const int cg = tid / TY;

    float acc[CPT][TX];
    #pragma unroll
    for (int c = 0; c < CPT; c++)
        #pragma unroll
        for (int x = 0; x < TX; x++) acc[c][x] = 0.0f;

    #pragma unroll 1
    for (int ci = 0; ci < CIN; ci++) {
        float w[CPT][9];
        #pragma unroll
        for (int c = 0; c < CPT; c++)
            #pragma unroll
            for (int k = 0; k < 9; k++)
                w[c][k] = sW[((cg*CPT + c)*CIN + ci)*9 + k];
        #pragma unroll
        for (int ky = 0; ky < 3; ky++) {
            const float* rp = &sIn[(ci*PH + y*STRIDE + ky)*PWP];
            float row[WR];
            #pragma unroll
            for (int j = 0; j < WR; j++) row[j] = rp[j];
            #pragma unroll
            for (int x = 0; x < TX; x++)
                #pragma unroll
                for (int kx = 0; kx < 3; kx++)
                    #pragma unroll
                    for (int c = 0; c < CPT; c++)
                        acc[c][x] = fmaf(row[x*STRIDE + kx], w[c][ky*3 + kx], acc[c][x]);
        }
    }

    #pragma unroll
    for (int c = 0; c < CPT; c++) {
        int co = co0 + cg*CPT + c;
        float bv = HB ? bias[co] : 0.0f;
        #pragma unroll
        for (int x = 0; x < TX; x++) {
            float v = acc[c][x] + bv;
            if (RELU) v = relu_(v);
            out[((b*Cout + co)*HOUT + oy0 + y)*WOUT + ox0 + x] = v;
        }
    }
}

// ---------------------------------------------------------------------------
// s0: in = concat(nearest(lqs,256), evs) [8,18,256,256] -> conv3x3 s2 p1 relu
//     -> [8,8,128,128]. Stage-once, gathered input. 128 thr, grid (64,1,8).
// ---------------------------------------------------------------------------
__global__ void s0f_kernel(const float* __restrict__ lqs, const float* __restrict__ evs,
                           const float* __restrict__ wt,  const float* __restrict__ bias,
                           float* __restrict__ out)
{
    constexpr int PH = 34, PW = 34, PWP = 35, NT = 128, TX = 16;
    extern __shared__ float sm[];
    float* sIn = sm;                 // 18*34*35
    float* sW  = sm + 18*PH*PWP;     // 8*18*9

    const int b   = blockIdx.z;
    const int ox0 = (blockIdx.x % 8) * 16;
    const int oy0 = (blockIdx.x / 8) * 16;
    const int tid = threadIdx.x;

    const int iy0 = oy0*2 - 1, ix0 = ox0*2 - 1;
    for (int i = tid; i < 18*PH*PW; i += NT) {
        int ci = i / (PH*PW); int rem = i - ci*(PH*PW);
        int r = rem / PW;     int c = rem - r*PW;
        int iy = iy0 + r, ix = ix0 + c;
        float v = 0.0f;
        if ((unsigned)iy < 256u && (unsigned)ix < 256u) {
            if (ci < 3) v = lqs[(b*3 + ci)*1048576 + iy*4096 + ix*4];  // nearest: src=4*dst
            else        v = evs[(b*15 + (ci-3))*65536 + iy*256 + ix];
        }
        sIn[(ci*PH + r)*PWP + c] = v;
    }
    for (int i = tid; i < 8*18*9; i += NT) sW[i] = wt[i];
    __syncthreads();

    const int y  = tid % 16;
    const int co = tid / 16;     // 0..7

    float acc[TX];
    #pragma unroll
    for (int x = 0; x < TX; x++) acc[x] = 0.0f;

    #pragma unroll 1
    for (int ci = 0; ci < 18; ci++) {
        float w[9];
        #pragma unroll
        for (int k = 0; k < 9; k++) w[k] = sW[(co*18 + ci)*9 + k];
        #pragma unroll
        for (int ky = 0; ky < 3; ky++) {
            const float* rp = &sIn[(ci*PH + y*2 + ky)*PWP];
            float row[33];
            #pragma unroll
            for (int j = 0; j < 33; j++) row[j] = rp[j];
            #pragma unroll
            for (int x = 0; x < TX; x++)
                #pragma unroll
                for (int kx = 0; kx < 3; kx++)
                    acc[x] = fmaf(row[x*2 + kx], w[ky*3 + kx], acc[x]);
        }
    }

    float bv = bias[co];
    #pragma unroll
    for (int x = 0; x < TX; x++)
        out[((b*8 + co)*128 + oy0 + y)*128 + ox0 + x] = relu_(acc[x] + bv);
}

// ---------------------------------------------------------------------------
// Fused cw1 (conv3x3 s2: [64,8,8]->[64,4,4]) + FC 1024->256->128->64.
// One block per batch, 256 threads. FC dots are warp-per-output, coalesced.
// ---------------------------------------------------------------------------
__global__ void cw1fc_kernel(const float* __restrict__ c0,
                             const float* __restrict__ cw1, const float* __restrict__ cb1,
                             const float* __restrict__ fw1, const float* __restrict__ fb1,
                             const float* __restrict__ fw2, const float* __restrict__ fb2,
                             const float* __restrict__ fw3, const float* __restrict__ fb3,
                             float* __restrict__ xg)
{
    extern __shared__ float sm[];
    float* sC  = sm;             // 64*10*11 = 7040
    float* sWt = sC + 7040;      // 36864
    float* sc1 = sWt + 36864;    // 1024
    float* s1f = sc1 + 1024;     // 256
    float* s2f = s1f + 256;      // 128

    const int b = blockIdx.x, tid = threadIdx.x;   // 256 threads

    for (int i = tid; i < 64*10*10; i += 256) {
        int ci = i / 100; int rem = i - ci*100;
        int r = rem / 10, c = rem - (rem/10)*10;
        int iy = r - 1, ix = c - 1;
        float v = 0.0f;
        if ((unsigned)iy < 8u && (unsigned)ix < 8u)
            v = c0[((b*64 + ci)*8 + iy)*8 + ix];
        sC[(ci*10 + r)*11 + c] = v;
    }
    for (int i = tid; i < 36864; i += 256) sWt[i] = cw1[i];
    __syncthreads();

    // c1 = relu(conv3x3 s2 (c0)) -> sc1[64*16] laid out co*16 + y*4 + x
    {
        int co = tid >> 2, y = tid & 3;
        float acc[4] = {0.0f, 0.0f, 0.0f, 0.0f};
        #pragma unroll 1
        for (int ci = 0; ci < 64; ci++) {
            float w[9];
            #pragma unroll
            for (int k = 0; k < 9; k++) w[k] = sWt[(co*64 + ci)*9 + k];
            #pragma unroll
            for (int ky = 0; ky < 3; ky++) {
                const float* rp = &sC[(ci*10 + y*2 + ky)*11];
                float row[9];
                #pragma unroll
                for (int j = 0; j < 9; j++) row[j] = rp[j];
                #pragma unroll
                for (int x = 0; x < 4; x++)
                    #pragma unroll
                    for (int kx = 0; kx < 3; kx++)
                        acc[x] = fmaf(row[x*2 + kx], w[ky*3 + kx], acc[x]);
            }
        }
        float bv = cb1[co];
        #pragma unroll
        for (int x = 0; x < 4; x++)
            sc1[co*16 + y*4 + x] = relu_(acc[x] + bv);
    }
    __syncthreads();

    const int lane = tid & 31, wp = tid >> 5;    // 8 warps

    // fc1: 256 outputs, warp-per-output (32 outputs per warp), coalesced reads
    for (int j = 0; j < 32; j++) {
        int o = wp*32 + j;
        const float* wr = fw1 + o*1024;
        float a = 0.0f;
        #pragma unroll 4
        for (int k = lane; k < 1024; k += 32) a = fmaf(wr[k], sc1[k], a);
        a = warp_sum(a);
        if (lane == 0) s1f[o] = relu_(a + fb1[o]);
    }
    __syncthreads();

    // fc2: 128 outputs
    for (int j = 0; j < 16; j++) {
        int o = wp*16 + j;
        const float* wr = fw2 + o*256;
        float a = 0.0f;
        #pragma unroll
        for (int k = lane; k < 256; k += 32) a = fmaf(wr[k], s1f[k], a);
        a = warp_sum(a);
        if (lane == 0) s2f[o] = relu_(a + fb2[o]);
    }
    __syncthreads();

    // fc3: 64 outputs
    for (int j = 0; j < 8; j++) {
        int o = wp*8 + j;
        const float* wr = fw3 + o*128;
        float a = 0.0f;
        #pragma unroll
        for (int k = lane; k < 128; k += 32) a = fmaf(wr[k], s2f[k], a);
        a = warp_sum(a);
        if (lane == 0) xg[b*64 + o] = a + fb3[o];
    }
}

// ---------------------------------------------------------------------------
// bg = conv1x1(relu(xg[b,c] + xl[b,c,y,x]), fuw) + fub  -> [B,8,16,16]
// ---------------------------------------------------------------------------
__global__ void bg_kernel(const float* __restrict__ xl, const float* __restrict__ xg,
                          const float* __restrict__ fuw, const float* __restrict__ fub,
                          float* __restrict__ bg)
{
    int b = blockIdx.x, p = threadIdx.x;   // 256 threads = 16x16 pixels
    __shared__ float sxg[64];
    __shared__ float sw[8*64];
    if (p < 64) sxg[p] = xg[b*64 + p];
    for (int i = p; i < 512; i += 256) sw[i] = fuw[i];
    __syncthreads();
    float acc[8];
    #pragma unroll
    for (int g = 0; g < 8; g++) acc[g] = fub[g];
    for (int c = 0; c < 64; c++) {
        float f = relu_(sxg[c] + xl[(b*64 + c)*256 + p]);
        #pragma unroll
        for (int g = 0; g < 8; g++) acc[g] = fmaf(sw[g*64 + c], f, acc[g]);
    }
    #pragma unroll
    for (int g = 0; g < 8; g++) bg[(b*8 + g)*256 + p] = acc[g];
}

// ---------------------------------------------------------------------------
// Fused highres kernel (unchanged from R5): blur + guide + trilinear slice.
// ---------------------------------------------------------------------------
__device__ __forceinline__ int reflect1024(int i) {
    return i < 0 ? -i : (i > 1023 ? 2046 - i : i);
}

__global__ __launch_bounds__(256, 2)
void highres_kernel(const float* __restrict__ lqs,
                    const float* __restrict__ gw1, const float* __restrict__ gb1,
                    const float* __restrict__ gw2, const float* __restrict__ gb2,
                    const float* __restrict__ bg,  float* __restrict__ out)
{
    __shared__ float sIn[3][48][49];
    __shared__ float sMid[3][48][33];
    __shared__ float sW[81];

    const int tid = threadIdx.x;
    const int bx = blockIdx.x*32, by = blockIdx.y*32, b = blockIdx.z;

    if (tid < 81)
        sW[tid] = (tid < 48) ? gw1[tid]
                : (tid < 64) ? gb1[tid - 48]
                : (tid < 80) ? gw2[tid - 64] : gb2[0];

    const float* base = lqs + b*3*1048576;

    for (int i = tid; i < 3*48*48; i += 256) {
        int ch = i / 2304; int rem = i - ch*2304;
        int r = rem / 48;  int c  = rem - r*48;
        sIn[ch][r][c] = base[ch*1048576 + reflect1024(by + r - 8)*1024 + reflect1024(bx + c - 8)];
    }
    __syncthreads();

    for (int s = tid; s < 288; s += 256) {
        int ch = s / 96; int rem = s - ch*96;
        int r = rem >> 1; int half = rem & 1;
        int c0 = half * 16;
        float w[32];
        #pragma unroll
        for (int j = 0; j < 32; j++) w[j] = sIn[ch][r][c0 + j];
        #pragma unroll
        for (int o = 0; o < 16; o++) {
            float a = 0.0f;
            #pragma unroll
            for (int k = 0; k < 17; k++) a = fmaf(GW[k], w[o + k], a);
            sMid[ch][r][c0 + o] = a;
        }
    }
    __syncthreads();

    const int tx = tid & 31;
    const int qy = tid >> 5;
    float vb[3][4];
    #pragma unroll
    for (int ch = 0; ch < 3; ch++) {
        float col[20];
        #pragma unroll
        for (int k = 0; k < 20; k++) col[k] = sMid[ch][qy*4 + k][tx];
        #pragma unroll
        for (int d = 0; d < 4; d++) {
            float a = 0.0f;
            #pragma unroll
            for (int k = 0; k < 17; k++) a = fmaf(GW[k], col[d + k], a);
            vb[ch][d] = a;
        }
    }

    const float* bgb = bg + b*2048;
    const int ox = bx + tx;
    const float gxv = (ox + 0.5f) * (1.0f/1024.0f) * 2.0f - 0.5f;
    const float xs = fminf(fmaxf(((gxv + 1.0f)*16.0f - 1.0f)*0.5f, 0.0f), 15.0f);
    const float x0f = floorf(xs);
    const int x0 = (int)x0f;
    const float fx = xs - x0f;
    const int x1 = min(x0 + 1, 15);

    #pragma unroll
    for (int d = 0; d < 4; d++) {
        float ssum = sW[80];
        #pragma unroll
        for (int o = 0; o < 16; o++) {
            float h = fmaf(sW[o*3], vb[0][d], fmaf(sW[o*3+1], vb[1][d], fmaf(sW[o*3+2], vb[2][d], sW[48+o])));
            h = relu_(h);
            ssum = fmaf(sW[64+o], h, ssum);
        }
        float sig = 1.0f / (1.0f + __expf(-ssum));
        float guide = 2.0f*sig - 0.5f;

        int oy = by + qy*4 + d;
        float gyv = (oy + 0.5f) * (1.0f/1024.0f) * 2.0f - 0.5f;
        float ys = fminf(fmaxf(((gyv + 1.0f)*16.0f - 1.0f)*0.5f, 0.0f), 15.0f);
        float zs = fminf(fmaxf(((guide + 1.0f)*8.0f - 1.0f)*0.5f, 0.0f), 7.0f);

        float y0f = floorf(ys), z0f = floorf(zs);
        int y0 = (int)y0f, z0 = (int)z0f;
        float fy = ys - y0f, fz = zs - z0f;
        int y1 = min(y0 + 1, 15), z1 = min(z0 + 1, 7);

        float v000 = __ldg(&bgb[z0*256 + y0*16 + x0]);
        float v001 = __ldg(&bgb[z0*256 + y0*16 + x1]);
        float v010 = __ldg(&bgb[z0*256 + y1*16 + x0]);
        float v011 = __ldg(&bgb[z0*256 + y1*16 + x1]);
        float v100 = __ldg(&bgb[z1*256 + y0*16 + x0]);
        float v101 = __ldg(&bgb[z1*256 + y0*16 + x1]);
        float v110 = __ldg(&bgb[z1*256 + y1*16 + x0]);
        float v111 = __ldg(&bgb[z1*256 + y1*16 + x1]);

        float c00 = v000 + (v001 - v000)*fx;
        float c01 = v010 + (v011 - v010)*fx;
        float c10 = v100 + (v101 - v100)*fx;
        float c11 = v110 + (v111 - v110)*fx;
        float c0v = c00 + (c01 - c00)*fy;
        float c1v = c10 + (c11 - c10)*fy;
        float val = c0v + (c1v - c0v)*fz;

        out[b*1048576 + oy*1024 + ox] = val;
    }
}

// ---------------------------------------------------------------------------
// kernel_launch
// ---------------------------------------------------------------------------
extern "C" void kernel_launch(void* const* d_in, const int* in_sizes, int n_in,
                              void* d_out, int out_size)
{
    const float* lqs = (const float*)d_in[0];
    const float* evs = (const float*)d_in[1];
    const float* gw1 = (const float*)d_in[2];
    const float* gb1 = (const float*)d_in[3];
    const float* gw2 = (const float*)d_in[4];
    const float* gb2 = (const float*)d_in[5];
    const float* sw0 = (const float*)d_in[6];
    const float* sb0 = (const float*)d_in[7];
    const float* sw1 = (const float*)d_in[8];
    const float* sb1 = (const float*)d_in[9];
    const float* sw2 = (const float*)d_in[10];
    const float* sb2 = (const float*)d_in[11];
    const float* sw3 = (const float*)d_in[12];
    const float* sb3 = (const float*)d_in[13];
    const float* cw0 = (const float*)d_in[14];
    const float* cb0 = (const float*)d_in[15];
    const float* cw1 = (const float*)d_in[16];
    const float* cb1 = (const float*)d_in[17];
    const float* fw1 = (const float*)d_in[18];
    const float* fb1 = (const float*)d_in[19];
    const float* fw2 = (const float*)d_in[20];
    const float* fb2 = (const float*)d_in[21];
    const float* fw3 = (const float*)d_in[22];
    const float* fb3 = (const float*)d_in[23];
    const float* lw1 = (const float*)d_in[24];
    const float* lb1 = (const float*)d_in[25];
    const float* lw2 = (const float*)d_in[26];
    const float* fuw = (const float*)d_in[27];
    const float* fub = (const float*)d_in[28];
    float* out = (float*)d_out;

    float *ps0, *ps1, *ps2, *ps3, *pl1, *pxl, *pc0, *pxg, *pbg;
    cudaGetSymbolAddress((void**)&ps0, g_s0);
    cudaGetSymbolAddress((void**)&ps1, g_s1);
    cudaGetSymbolAddress((void**)&ps2, g_s2);
    cudaGetSymbolAddress((void**)&ps3, g_s3);
    cudaGetSymbolAddress((void**)&pl1, g_l1);
    cudaGetSymbolAddress((void**)&pxl, g_xl);
    cudaGetSymbolAddress((void**)&pc0, g_c0);
    cudaGetSymbolAddress((void**)&pxg, g_xg);
    cudaGetSymbolAddress((void**)&pbg, g_bg);

    // Dynamic smem sizes (bytes)
    const int SM_S0  = (18*34*35 + 8*18*9)  * 4;  //  90864
    const int SM_S1  = (8*34*35  + 16*8*9)  * 4;  //  42688
    const int SM_S2  = (16*34*35 + 16*16*9) * 4;  //  85376
    const int SM_S3  = (32*34*35 + 16*32*9) * 4;  // 170752
    const int SM_LW  = (64*18*19 + 8*64*9)  * 4;  // 105984
    const int SM_CW0 = (64*18*19 + 16*64*9) * 4;  // 124416
    const int SM_FC  = (64*10*11 + 36864 + 1024 + 256 + 128) * 4;  // 181248

    cudaFuncSetAttribute(s0f_kernel, cudaFuncAttributeMaxDynamicSharedMemorySize, SM_S0);
    cudaFuncSetAttribute(convf_kernel<8,2,16,1,16,16,true,true>,  cudaFuncAttributeMaxDynamicSharedMemorySize, SM_S1);
    cudaFuncSetAttribute(convf_kernel<16,2,16,1,16,16,true,true>, cudaFuncAttributeMaxDynamicSharedMemorySize, SM_S2);
    cudaFuncSetAttribute(convf_kernel<32,2,16,2,16,16,true,true>, cudaFuncAttributeMaxDynamicSharedMemorySize, SM_S3);
    cudaFuncSetAttribute(convf_kernel<64,1,8,1,16,16,true,true>,  cudaFuncAttributeMaxDynamicSharedMemorySize, SM_LW);
    cudaFuncSetAttribute(convf_kernel<64,1,8,1,16,16,false,false>,cudaFuncAttributeMaxDynamicSharedMemorySize, SM_LW);
    cudaFuncSetAttribute(convf_kernel<64,2,16,1,8,8,true,true>,   cudaFuncAttributeMaxDynamicSharedMemorySize, SM_CW0);
    cudaFuncSetAttribute(cw1fc_kernel, cudaFuncAttributeMaxDynamicSharedMemorySize, SM_FC);

    // ---- lowres path (stage-once, wide-parallel) ----
    s0f_kernel<<<dim3(64, 1, 8), 128, SM_S0>>>(lqs, evs, sw0, sb0, ps0);
    convf_kernel<8,2,16,1,16,16,true,true><<<dim3(16, 1, 8), 256, SM_S1>>>(ps0, sw1, sb1, ps1, 128, 128, 16, 64, 64, 4);
    convf_kernel<16,2,16,1,16,16,true,true><<<dim3(4, 2, 8), 256, SM_S2>>>(ps1, sw2, sb2, ps2, 64, 64, 32, 32, 32, 2);
    convf_kernel<32,2,16,2,16,16,true,true><<<dim3(1, 4, 8), 128, SM_S3>>>(ps2, sw3, sb3, ps3, 32, 32, 64, 16, 16, 1);
    // local head
    convf_kernel<64,1,8,1,16,16,true,true><<<dim3(1, 8, 8), 128, SM_LW>>>(ps3, lw1, lb1, pl1, 16, 16, 64, 16, 16, 1);
    convf_kernel<64,1,8,1,16,16,false,false><<<dim3(1, 8, 8), 128, SM_LW>>>(pl1, lw2, (const float*)nullptr, pxl, 16, 16, 64, 16, 16, 1);
    // global head
    convf_kernel<64,2,16,1,8,8,true,true><<<dim3(1, 4, 8), 128, SM_CW0>>>(ps3, cw0, cb0, pc0, 16, 16, 64, 8, 8, 1);
    cw1fc_kernel<<<8, 256, SM_FC>>>(pc0, cw1, cb1, fw1, fb1, fw2, fb2, fw3, fb3, pxg);
    bg_kernel<<<8, 256>>>(pxl, pxg, fuw, fub, pbg);

    // ---- fused highres: blur + guide + slice ----
    highres_kernel<<<dim3(32, 32, 8), 256>>>(lqs, gw1, gb1, gw2, gb2, pbg, out);
}

// round 11
// speedup vs baseline: 1.1246x; 1.0397x over previous
#include <cuda_runtime.h>

// ---------------------------------------------------------------------------
// Scratch (no allocation allowed -> __device__ globals)
// ---------------------------------------------------------------------------
static __device__ float g_s0[8*8*128*128];    // conv s0 out [8,8,128,128]
static __device__ float g_s1[8*16*64*64];     // [8,16,64,64]
static __device__ float g_s2[8*32*32*32];     // [8,32,32,32]
static __device__ float g_s3[8*64*16*16];     // [8,64,16,16]
static __device__ float g_l1[8*64*16*16];     // lw1 out
static __device__ float g_xl[8*64*16*16];     // lw2 out (local head)
static __device__ float g_c0[8*64*8*8];       // cw0 out
static __device__ float g_xg[8*64];           // fc3 out
static __device__ float g_bg[8*8*16*16];      // bilateral grid [B,8,16,16]
static __device__ float g_guide[8*1024*1024]; // guide map [B,1024,1024]

__device__ __forceinline__ float relu_(float x){ return fmaxf(x, 0.0f); }

__device__ __forceinline__ float warp_sum(float v){
    #pragma unroll
    for (int o = 16; o > 0; o >>= 1) v += __shfl_down_sync(0xffffffffu, v, o);
    return v;
}

// Gaussian(sigma=2), 17 taps, normalized. Compile-time literals -> FFMA-imm.
static __device__ constexpr float GW[17] = {
    6.691630e-05f, 4.363500e-04f, 2.215960e-03f, 8.764310e-03f,
    2.699596e-02f, 6.475993e-02f, 1.209875e-01f, 1.760357e-01f,
    1.994747e-01f,
    1.760357e-01f, 1.209875e-01f, 6.475993e-02f, 2.699596e-02f,
    8.764310e-03f, 2.215960e-03f, 4.363500e-04f, 6.691630e-05f
};

// ---------------------------------------------------------------------------
// convf2: 3x3 conv (pad=1, stride S). Chunked smem staging (CICH ci planes),
// thread = (co-group cg, x-group xg, row y), TX outputs along x per thread,
// CPT output channels per thread. Warp spans (y, cg) -> window LDS broadcast,
// weight LDS on distinct banks via padded stride SWS.
// ---------------------------------------------------------------------------
template<int CIN, int CICH, int S, int COB, int CPT, int TY, int TX, int XG,
         bool RELU, bool HB>
__global__ void convf2_kernel(const float* __restrict__ in, const float* __restrict__ wt,
                              const float* __restrict__ bias, float* __restrict__ out,
                              int HIN, int WIN, int Cout, int HOUT, int WOUT, int tilesX)
{
    constexpr int TILEW = TX*XG;
    constexpr int PH  = (TY-1)*S + 3;
    constexpr int PW  = (TILEW-1)*S + 3;
    constexpr int PWP = (PW % 2 == 0) ? PW + 1 : PW;
    constexpr int CG  = COB/CPT;
    constexpr int NT  = CG*TY*XG;
    constexpr int WR  = (TX-1)*S + 3;
    constexpr int SWS = CICH*9 + 1;          // padded weight stride per co

    extern __shared__ float sm[];
    float* sIn = sm;                          // CICH*PH*PWP
    float* sW  = sm + CICH*PH*PWP;            // COB*SWS

    const int b     = blockIdx.z;
    const int co0   = blockIdx.y * COB;
    const int tileX = (blockIdx.x % tilesX) * TILEW;
    const int tileY = (blockIdx.x / tilesX) * TY;
    const int tid   = threadIdx.x;

    const int y  = tid % TY;
    const int cg = (tid / TY) % CG;
    const int xg = tid / (TY*CG);

    float acc[CPT][TX];
    #pragma unroll
    for (int c = 0; c < CPT; c++)
        #pragma unroll
        for (int x = 0; x < TX; x++) acc[c][x] = 0.0f;

    const int iy0 = tileY*S - 1, ix0 = tileX*S - 1;

    #pragma unroll 1
    for (int ci0 = 0; ci0 < CIN; ci0 += CICH) {
        for (int i = tid; i < CICH*PH*PW; i += NT) {
            int ci = i / (PH*PW); int rem = i - ci*(PH*PW);
            int r = rem / PW;     int c = rem - r*PW;
            int iy = iy0 + r, ix = ix0 + c;
            float v = 0.0f;
            if ((unsigned)iy < (unsigned)HIN && (unsigned)ix < (unsigned)WIN)
                v = in[((b*CIN + ci0 + ci)*HIN + iy)*WIN + ix];
            sIn[(ci*PH + r)*PWP + c] = v;
        }
        for (int i = tid; i < COB*CICH*9; i += NT) {
            int co = i / (CICH*9); int rem = i - co*(CICH*9);
            int ci = rem / 9;      int k = rem - ci*9;
            sW[co*SWS + ci*9 + k] = wt[((co0 + co)*CIN + ci0 + ci)*9 + k];
        }
        __syncthreads();

        #pragma unroll
        for (int ci = 0; ci < CICH; ci++) {
            float w[CPT][9];
            #pragma unroll
            for (int c = 0; c < CPT; c++)
                #pragma unroll
                for (int k = 0; k < 9; k++)
                    w[c][k] = sW[(cg*CPT + c)*SWS + ci*9 + k];
            #pragma unroll
            for (int ky = 0; ky < 3; ky++) {
                const float* rp = &sIn[(ci*PH + y*S + ky)*PWP + xg*TX*S];
                float row[WR];
                #pragma unroll
                for (int j = 0; j < WR; j++) row[j] = rp[j];
                #pragma unroll
                for (int x = 0; x < TX; x++)
                    #pragma unroll
                    for (int kx = 0; kx < 3; kx++)
                        #pragma unroll
                        for (int c = 0; c < CPT; c++)
                            acc[c][x] = fmaf(row[x*S + kx], w[c][ky*3 + kx], acc[c][x]);
            }
        }
        __syncthreads();
    }

    #pragma unroll
    for (int c = 0; c < CPT; c++) {
        int co = co0 + cg*CPT + c;
        float bv = HB ? bias[co] : 0.0f;
        #pragma unroll
        for (int x = 0; x < TX; x++) {
            float v = acc[c][x] + bv;
            if (RELU) v = relu_(v);
            out[((b*Cout + co)*HOUT + tileY + y)*WOUT + tileX + xg*TX + x] = v;
        }
    }
}

// ---------------------------------------------------------------------------
// s0: in = concat(nearest(lqs,256), evs) [8,18,256,256] -> conv3x3 s2 p1 relu
//     -> [8,8,128,128]. Chunked (CICH=3) gathered staging. 128 thr, 512 blocks.
// ---------------------------------------------------------------------------
__global__ void s0f_kernel(const float* __restrict__ lqs, const float* __restrict__ evs,
                           const float* __restrict__ wt,  const float* __restrict__ bias,
                           float* __restrict__ out)
{
    constexpr int PH = 33, PW = 33, PWP = 33, NT = 128, SWS = 18*9 + 1;
    extern __shared__ float sm[];
    float* sIn = sm;                 // 3*33*33
    float* sW  = sm + 3*PH*PWP;      // 8*SWS

    const int b     = blockIdx.z;
    const int tileX = (blockIdx.x % 8) * 16;
    const int tileY = (blockIdx.x / 8) * 16;
    const int tid   = threadIdx.x;

    const int y  = tid % 16;
    const int cg = (tid / 16) % 4;   // co group (2 co each)
    const int xg = tid / 64;         // 0..1

    // stage all weights once (padded stride)
    for (int i = tid; i < 8*18*9; i += NT) {
        int co = i / 162; int rem = i - co*162;
        sW[co*SWS + rem] = wt[i];
    }

    float acc[2][8];
    #pragma unroll
    for (int c = 0; c < 2; c++)
        #pragma unroll
        for (int x = 0; x < 8; x++) acc[c][x] = 0.0f;

    const int iy0 = tileY*2 - 1, ix0 = tileX*2 - 1;

    #pragma unroll 1
    for (int c0 = 0; c0 < 18; c0 += 3) {
        for (int i = tid; i < 3*PH*PW; i += NT) {
            int ci = i / (PH*PW); int rem = i - ci*(PH*PW);
            int r = rem / PW;     int c = rem - r*PW;
            int iy = iy0 + r, ix = ix0 + c;
            float v = 0.0f;
            if ((unsigned)iy < 256u && (unsigned)ix < 256u) {
                int ch = c0 + ci;
                if (ch < 3) v = lqs[(b*3 + ch)*1048576 + iy*4096 + ix*4];  // nearest: src=4*dst
                else        v = evs[(b*15 + (ch-3))*65536 + iy*256 + ix];
            }
            sIn[(ci*PH + r)*PWP + c] = v;
        }
        __syncthreads();

        #pragma unroll
        for (int ci = 0; ci < 3; ci++) {
            int gci = c0 + ci;
            float w[2][9];
            #pragma unroll
            for (int c = 0; c < 2; c++)
                #pragma unroll
                for (int k = 0; k < 9; k++)
                    w[c][k] = sW[(cg*2 + c)*SWS + gci*9 + k];
            #pragma unroll
            for (int ky = 0; ky < 3; ky++) {
                const float* rp = &sIn[(ci*PH + y*2 + ky)*PWP + xg*16];
                float row[17];
                #pragma unroll
                for (int j = 0; j < 17; j++) row[j] = rp[j];
                #pragma unroll
                for (int x = 0; x < 8; x++)
                    #pragma unroll
                    for (int kx = 0; kx < 3; kx++)
                        #pragma unroll
                        for (int c = 0; c < 2; c++)
                            acc[c][x] = fmaf(row[x*2 + kx], w[c][ky*3 + kx], acc[c][x]);
            }
        }
        __syncthreads();
    }

    #pragma unroll
    for (int c = 0; c < 2; c++) {
        int co = cg*2 + c;
        float bv = bias[co];
        #pragma unroll
        for (int x = 0; x < 8; x++)
            out[((b*8 + co)*128 + tileY + y)*128 + tileX + xg*8 + x] = relu_(acc[c][x] + bv);
    }
}

// ---------------------------------------------------------------------------
// Fused cw1 (conv3x3 s2: [64,8,8]->[64,4,4]) + FC 1024->256->128->64.
// One block per batch, 256 threads. FC dots warp-per-output, coalesced.
// ---------------------------------------------------------------------------
__global__ void cw1fc_kernel(const float* __restrict__ c0,
                             const float* __restrict__ cw1, const float* __restrict__ cb1,
                             const float* __restrict__ fw1, const float* __restrict__ fb1,
                             const float* __restrict__ fw2, const float* __restrict__ fb2,
                             const float* __restrict__ fw3, const float* __restrict__ fb3,
                             float* __restrict__ xg)
{
    extern __shared__ float sm[];
    float* sC  = sm;             // 64*10*11 = 7040
    float* sWt = sC + 7040;      // 36864
    float* sc1 = sWt + 36864;    // 1024
    float* s1f = sc1 + 1024;     // 256
    float* s2f = s1f + 256;      // 128

    const int b = blockIdx.x, tid = threadIdx.x;   // 256 threads

    for (int i = tid; i < 64*10*10; i += 256) {
        int ci = i / 100; int rem = i - ci*100;
        int r = rem / 10, c = rem - (rem/10)*10;
        int iy = r - 1, ix = c - 1;
        float v = 0.0f;
        if ((unsigned)iy < 8u && (unsigned)ix < 8u)
            v = c0[((b*64 + ci)*8 + iy)*8 + ix];
        sC[(ci*10 + r)*11 + c] = v;
    }
    for (int i = tid; i < 36864; i += 256) sWt[i] = cw1[i];
    __syncthreads();

    {
        int co = tid >> 2, y = tid & 3;
        float acc[4] = {0.0f, 0.0f, 0.0f, 0.0f};
        #pragma unroll 1
        for (int ci = 0; ci < 64; ci++) {
            float w[9];
            #pragma unroll
            for (int k = 0; k < 9; k++) w[k] = sWt[(co*64 + ci)*9 + k];
            #pragma unroll
            for (int ky = 0; ky < 3; ky++) {
                const float* rp = &sC[(ci*10 + y*2 + ky)*11];
                float row[9];
                #pragma unroll
                for (int j = 0; j < 9; j++) row[j] = rp[j];
                #pragma unroll
                for (int x = 0; x < 4; x++)
                    #pragma unroll
                    for (int kx = 0; kx < 3; kx++)
                        acc[x] = fmaf(row[x*2 + kx], w[ky*3 + kx], acc[x]);
            }
        }
        float bv = cb1[co];
        #pragma unroll
        for (int x = 0; x < 4; x++)
            sc1[co*16 + y*4 + x] = relu_(acc[x] + bv);
    }
    __syncthreads();

    const int lane = tid & 31, wp = tid >> 5;    // 8 warps

    for (int j = 0; j < 32; j++) {
        int o = wp*32 + j;
        const float* wr = fw1 + o*1024;
        float a = 0.0f;
        #pragma unroll 4
        for (int k = lane; k < 1024; k += 32) a = fmaf(wr[k], sc1[k], a);
        a = warp_sum(a);
        if (lane == 0) s1f[o] = relu_(a + fb1[o]);
    }
    __syncthreads();

    for (int j = 0; j < 16; j++) {
        int o = wp*16 + j;
        const float* wr = fw2 + o*256;
        float a = 0.0f;
        #pragma unroll
        for (int k = lane; k < 256; k += 32) a = fmaf(wr[k], s1f[k], a);
        a = warp_sum(a);
        if (lane == 0) s2f[o] = relu_(a + fb2[o]);
    }
    __syncthreads();

    for (int j = 0; j < 8; j++) {
        int o = wp*8 + j;
        const float* wr = fw3 + o*128;
        float a = 0.0f;
        #pragma unroll
        for (int k = lane; k < 128; k += 32) a = fmaf(wr[k], s2f[k], a);
        a = warp_sum(a);
        if (lane == 0) xg[b*64 + o] = a + fb3[o];
    }
}

// ---------------------------------------------------------------------------
// bg = conv1x1(relu(xg[b,c] + xl[b,c,y,x]), fuw) + fub  -> [B,8,16,16]
// ---------------------------------------------------------------------------
__global__ void bg_kernel(const float* __restrict__ xl, const float* __restrict__ xg,
                          const float* __restrict__ fuw, const float* __restrict__ fub,
                          float* __restrict__ bg)
{
    int b = blockIdx.x, p = threadIdx.x;   // 256 threads = 16x16 pixels
    __shared__ float sxg[64];
    __shared__ float sw[8*64];
    if (p < 64) sxg[p] = xg[b*64 + p];
    for (int i = p; i < 512; i += 256) sw[i] = fuw[i];
    __syncthreads();
    float acc[8];
    #pragma unroll
    for (int g = 0; g < 8; g++) acc[g] = fub[g];
    for (int c = 0; c < 64; c++) {
        float f = relu_(sxg[c] + xl[(b*64 + c)*256 + p]);
        #pragma unroll
        for (int g = 0; g < 8; g++) acc[g] = fmaf(sw[g*64 + c], f, acc[g]);
    }
    #pragma unroll
    for (int g = 0; g < 8; g++) bg[(b*8 + g)*256 + p] = acc[g];
}

// ---------------------------------------------------------------------------
// guide_kernel: Gaussian blur (separable, reflect) + 1x1 convs -> guide map.
// (highres front half; no bg dependency -> runs concurrent with lowres chain)
// ---------------------------------------------------------------------------
__device__ __forceinline__ int reflect1024(int i) {
    return i < 0 ? -i : (i > 1023 ? 2046 - i : i);
}

__global__ __launch_bounds__(256, 2)
void guide_kernel(const float* __restrict__ lqs,
                  const float* __restrict__ gw1, const float* __restrict__ gb1,
                  const float* __restrict__ gw2, const float* __restrict__ gb2,
                  float* __restrict__ guide)
{
    __shared__ float sIn[3][48][49];
    __shared__ float sMid[3][48][33];
    __shared__ float sW[81];

    const int tid = threadIdx.x;
    const int bx = blockIdx.x*32, by = blockIdx.y*32, b = blockIdx.z;

    if (tid < 81)
        sW[tid] = (tid < 48) ? gw1[tid]
                : (tid < 64) ? gb1[tid - 48]
                : (tid < 80) ? gw2[tid - 64] : gb2[0];

    const float* base = lqs + b*3*1048576;

    for (int i = tid; i < 3*48*48; i += 256) {
        int ch = i / 2304; int rem = i - ch*2304;
        int r = rem / 48;  int c  = rem - r*48;
        sIn[ch][r][c] = base[ch*1048576 + reflect1024(by + r - 8)*1024 + reflect1024(bx + c - 8)];
    }
    __syncthreads();

    for (int s = tid; s < 288; s += 256) {
        int ch = s / 96; int rem = s - ch*96;
        int r = rem >> 1; int half = rem & 1;
        int c0 = half * 16;
        float w[32];
        #pragma unroll
        for (int j = 0; j < 32; j++) w[j] = sIn[ch][r][c0 + j];
        #pragma unroll
        for (int o = 0; o < 16; o++) {
            float a = 0.0f;
            #pragma unroll
            for (int k = 0; k < 17; k++) a = fmaf(GW[k], w[o + k], a);
            sMid[ch][r][c0 + o] = a;
        }
    }
    __syncthreads();

    const int tx = tid & 31;
    const int qy = tid >> 5;
    float vb[3][4];
    #pragma unroll
    for (int ch = 0; ch < 3; ch++) {
        float col[20];
        #pragma unroll
        for (int k = 0; k < 20; k++) col[k] = sMid[ch][qy*4 + k][tx];
        #pragma unroll
        for (int d = 0; d < 4; d++) {
            float a = 0.0f;
            #pragma unroll
            for (int k = 0; k < 17; k++) a = fmaf(GW[k], col[d + k], a);
            vb[ch][d] = a;
        }
    }

    const int ox = bx + tx;
    #pragma unroll
    for (int d = 0; d < 4; d++) {
        float ssum = sW[80];
        #pragma unroll
        for (int o = 0; o < 16; o++) {
            float h = fmaf(sW[o*3], vb[0][d], fmaf(sW[o*3+1], vb[1][d], fmaf(sW[o*3+2], vb[2][d], sW[48+o])));
            h = relu_(h);
            ssum = fmaf(sW[64+o], h, ssum);
        }
        float sig = 1.0f / (1.0f + __expf(-ssum));
        int oy = by + qy*4 + d;
        guide[b*1048576 + oy*1024 + ox] = 2.0f*sig - 0.5f;
    }
}

// ---------------------------------------------------------------------------
// slice_kernel: trilinear slice of bilateral grid using guide map. float4 I/O.
// ---------------------------------------------------------------------------
__global__ void slice_kernel(const float* __restrict__ guide,
                             const float* __restrict__ bg, float* __restrict__ out)
{
    int idx = blockIdx.x*256 + threadIdx.x;     // 2,097,152 threads (x4 px)
    int b   = idx >> 18;
    int rem = idx & 0x3FFFF;
    int py  = rem >> 8;
    int px0 = (rem & 255) << 2;

    float4 g4 = ((const float4*)guide)[idx];
    float gv[4] = {g4.x, g4.y, g4.z, g4.w};

    float gyv = (py + 0.5f) * (1.0f/1024.0f) * 2.0f - 0.5f;
    float ys  = fminf(fmaxf(((gyv + 1.0f)*16.0f - 1.0f)*0.5f, 0.0f), 15.0f);
    float y0f = floorf(ys);
    int   y0  = (int)y0f;
    float fy  = ys - y0f;
    int   y1  = min(y0 + 1, 15);

    const float* bgb = bg + b*2048;
    float res[4];
    #pragma unroll
    for (int j = 0; j < 4; j++) {
        int px = px0 + j;
        float gxv = (px + 0.5f) * (1.0f/1024.0f) * 2.0f - 0.5f;
        float xs  = fminf(fmaxf(((gxv + 1.0f)*16.0f - 1.0f)*0.5f, 0.0f), 15.0f);
        float x0f = floorf(xs);
        int   x0  = (int)x0f;
        float fx  = xs - x0f;
        int   x1  = min(x0 + 1, 15);

        float zs  = fminf(fmaxf(((gv[j] + 1.0f)*8.0f - 1.0f)*0.5f, 0.0f), 7.0f);
        float z0f = floorf(zs);
        int   z0  = (int)z0f;
        float fz  = zs - z0f;
        int   z1  = min(z0 + 1, 7);

        float v000 = __ldg(&bgb[z0*256 + y0*16 + x0]);
        float v001 = __ldg(&bgb[z0*256 + y0*16 + x1]);
        float v010 = __ldg(&bgb[z0*256 + y1*16 + x0]);
        float v011 = __ldg(&bgb[z0*256 + y1*16 + x1]);
        float v100 = __ldg(&bgb[z1*256 + y0*16 + x0]);
        float v101 = __ldg(&bgb[z1*256 + y0*16 + x1]);
        float v110 = __ldg(&bgb[z1*256 + y1*16 + x0]);
        float v111 = __ldg(&bgb[z1*256 + y1*16 + x1]);

        float c00 = v000 + (v001 - v000)*fx;
        float c01 = v010 + (v011 - v010)*fx;
        float c10 = v100 + (v101 - v100)*fx;
        float c11 = v110 + (v111 - v110)*fx;
        float c0v = c00 + (c01 - c00)*fy;
        float c1v = c10 + (c11 - c10)*fy;
        res[j] = c0v + (c1v - c0v)*fz;
    }
    ((float4*)out)[idx] = make_float4(res[0], res[1], res[2], res[3]);
}

// ---------------------------------------------------------------------------
// kernel_launch
// ---------------------------------------------------------------------------
extern "C" void kernel_launch(void* const* d_in, const int* in_sizes, int n_in,
                              void* d_out, int out_size)
{
    const float* lqs = (const float*)d_in[0];
    const float* evs = (const float*)d_in[1];
    const float* gw1 = (const float*)d_in[2];
    const float* gb1 = (const float*)d_in[3];
    const float* gw2 = (const float*)d_in[4];
    const float* gb2 = (const float*)d_in[5];
    const float* sw0 = (const float*)d_in[6];
    const float* sb0 = (const float*)d_in[7];
    const float* sw1 = (const float*)d_in[8];
    const float* sb1 = (const float*)d_in[9];
    const float* sw2 = (const float*)d_in[10];
    const float* sb2 = (const float*)d_in[11];
    const float* sw3 = (const float*)d_in[12];
    const float* sb3 = (const float*)d_in[13];
    const float* cw0 = (const float*)d_in[14];
    const float* cb0 = (const float*)d_in[15];
    const float* cw1 = (const float*)d_in[16];
    const float* cb1 = (const float*)d_in[17];
    const float* fw1 = (const float*)d_in[18];
    const float* fb1 = (const float*)d_in[19];
    const float* fw2 = (const float*)d_in[20];
    const float* fb2 = (const float*)d_in[21];
    const float* fw3 = (const float*)d_in[22];
    const float* fb3 = (const float*)d_in[23];
    const float* lw1 = (const float*)d_in[24];
    const float* lb1 = (const float*)d_in[25];
    const float* lw2 = (const float*)d_in[26];
    const float* fuw = (const float*)d_in[27];
    const float* fub = (const float*)d_in[28];
    float* out = (float*)d_out;

    float *ps0, *ps1, *ps2, *ps3, *pl1, *pxl, *pc0, *pxg, *pbg, *pgd;
    cudaGetSymbolAddress((void**)&ps0, g_s0);
    cudaGetSymbolAddress((void**)&ps1, g_s1);
    cudaGetSymbolAddress((void**)&ps2, g_s2);
    cudaGetSymbolAddress((void**)&ps3, g_s3);
    cudaGetSymbolAddress((void**)&pl1, g_l1);
    cudaGetSymbolAddress((void**)&pxl, g_xl);
    cudaGetSymbolAddress((void**)&pc0, g_c0);
    cudaGetSymbolAddress((void**)&pxg, g_xg);
    cudaGetSymbolAddress((void**)&pbg, g_bg);
    cudaGetSymbolAddress((void**)&pgd, g_guide);

    // Lazy one-time side stream + events (created on the uncaptured
    // correctness call; reused identically on every call after).
    static cudaStream_t s_side = nullptr;
    static cudaEvent_t  ev_fork = nullptr, ev_join = nullptr;
    if (!s_side) {
        cudaStreamCreateWithFlags(&s_side, cudaStreamNonBlocking);
        cudaEventCreateWithFlags(&ev_fork, cudaEventDisableTiming);
        cudaEventCreateWithFlags(&ev_join, cudaEventDisableTiming);
        cudaFuncSetAttribute(cw1fc_kernel, cudaFuncAttributeMaxDynamicSharedMemorySize,
                             (7040 + 36864 + 1024 + 256 + 128) * 4);
    }

    // Dynamic smem sizes (bytes)
    const int SM_S0  = (3*33*33 + 8*163) * 4;       // 18284
    const int SM_S1  = (8*33*33 + 16*73) * 4;       // 39520
    const int SM_S2  = (8*33*33 + 16*73) * 4;       // 39520
    const int SM_S3  = (8*33*33 + 8*73)  * 4;       // 37184
    const int SM_LW  = (16*18*19 + 4*145) * 4;      // 24208
    const int SM_CW0 = (16*17*17 + 8*145) * 4;      // 23136
    const int SM_FC  = (7040 + 36864 + 1024 + 256 + 128) * 4;  // 181248

    // ---- fork: guide path runs concurrent with the lowres chain ----
    cudaEventRecord(ev_fork, 0);
    cudaStreamWaitEvent(s_side, ev_fork, 0);
    guide_kernel<<<dim3(32, 32, 8), 256, 0, s_side>>>(lqs, gw1, gb1, gw2, gb2, pgd);

    // ---- lowres path (chunk-staged convf2, small smem, many blocks) ----
    s0f_kernel<<<dim3(64, 1, 8), 128, SM_S0>>>(lqs, evs, sw0, sb0, ps0);
    convf2_kernel<8,8,2, 16,2,16,16,1, true,true>
        <<<dim3(16, 1, 8), 128, SM_S1>>>(ps0, sw1, sb1, ps1, 128, 128, 16, 64, 64, 4);
    convf2_kernel<16,8,2, 16,2,16,16,1, true,true>
        <<<dim3(4, 2, 8), 128, SM_S2>>>(ps1, sw2, sb2, ps2, 64, 64, 32, 32, 32, 2);
    convf2_kernel<32,8,2, 8,2,16,8,2, true,true>
        <<<dim3(1, 8, 8), 128, SM_S3>>>(ps2, sw3, sb3, ps3, 32, 32, 64, 16, 16, 1);
    // local head
    convf2_kernel<64,16,1, 4,1,16,8,2, true,true>
        <<<dim3(1, 16, 8), 128, SM_LW>>>(ps3, lw1, lb1, pl1, 16, 16, 64, 16, 16, 1);
    convf2_kernel<64,16,1, 4,1,16,8,2, false,false>
        <<<dim3(1, 16, 8), 128, SM_LW>>>(pl1, lw2, (const float*)nullptr, pxl, 16, 16, 64, 16, 16, 1);
    // global head
    convf2_kernel<64,16,2, 8,2,8,4,2, true,true>
        <<<dim3(1, 8, 8), 64, SM_CW0>>>(ps3, cw0, cb0, pc0, 16, 16, 64, 8, 8, 1);
    cw1fc_kernel<<<8, 256, SM_FC>>>(pc0, cw1, cb1, fw1, fb1, fw2, fb2, fw3, fb3, pxg);
    bg_kernel<<<8, 256>>>(pxl, pxg, fuw, fub, pbg);

    // ---- join: slice needs both guide (side) and bg (main) ----
    cudaEventRecord(ev_join, s_side);
    cudaStreamWaitEvent(0, ev_join, 0);
    slice_kernel<<<8192, 256>>>(pgd, pbg, out);
}

// round 12
// speedup vs baseline: 1.4845x; 1.3200x over previous
#include <cuda_runtime.h>

// ---------------------------------------------------------------------------
// Scratch (no allocation allowed -> __device__ globals)
// ---------------------------------------------------------------------------
static __device__ float g_s0[8*8*128*128];    // conv s0 out [8,8,128,128]
static __device__ float g_s1[8*16*64*64];     // [8,16,64,64]
static __device__ float g_s2[8*32*32*32];     // [8,32,32,32]
static __device__ float g_s3[8*64*16*16];     // [8,64,16,16]
static __device__ float g_l1[8*64*16*16];     // lw1 out
static __device__ float g_xl[8*64*16*16];     // lw2 out (local head)
static __device__ float g_c0[8*64*8*8];       // cw0 out
static __device__ float g_xg[8*64];           // fc3 out
static __device__ float g_bg[8*8*16*16];      // bilateral grid [B,8,16,16]
static __device__ float g_guide[8*1024*1024]; // guide map [B,1024,1024]

__device__ __forceinline__ float relu_(float x){ return fmaxf(x, 0.0f); }

__device__ __forceinline__ float warp_sum(float v){
    #pragma unroll
    for (int o = 16; o > 0; o >>= 1) v += __shfl_down_sync(0xffffffffu, v, o);
    return v;
}

// Gaussian(sigma=2), 17 taps, normalized. Compile-time literals -> FFMA-imm.
static __device__ constexpr float GW[17] = {
    6.691630e-05f, 4.363500e-04f, 2.215960e-03f, 8.764310e-03f,
    2.699596e-02f, 6.475993e-02f, 1.209875e-01f, 1.760357e-01f,
    1.994747e-01f,
    1.760357e-01f, 1.209875e-01f, 6.475993e-02f, 2.699596e-02f,
    8.764310e-03f, 2.215960e-03f, 4.363500e-04f, 6.691630e-05f
};

// ---------------------------------------------------------------------------
// convf3: 3x3 conv (pad=1, stride S). Whole input staged ONCE per block with
// register-batched loads (8 LDG in flight -> 8 STS), 256 threads, one sync.
// Thread = (x-group xg, co-group cg, row y); TX outputs per thread, CPT co.
// ---------------------------------------------------------------------------
template<int CIN, int S, int COB, int CPT, int TY, int TX, int XG, bool RELU, bool HB>
__global__ void convf3_kernel(const float* __restrict__ in, const float* __restrict__ wt,
                              const float* __restrict__ bias, float* __restrict__ out,
                              int HIN, int WIN, int Cout, int HOUT, int WOUT, int tilesX)
{
    constexpr int TILEW = TX*XG;
    constexpr int PH  = (TY-1)*S + 3;
    constexpr int PW  = (TILEW-1)*S + 3;
    constexpr int PWP = (PW % 2 == 0) ? PW + 1 : PW;   // odd stride -> conflict-free
    constexpr int CG  = COB/CPT;
    constexpr int NT  = CG*TY*XG;                      // = 256 in all uses
    constexpr int WR  = (TX-1)*S + 3;
    constexpr int TOT = CIN*PH*PW;
    constexpr int WTOT = COB*CIN*9;
    constexpr int NB  = (TOT + NT*8 - 1)/(NT*8);

    extern __shared__ float sm[];
    float* sIn = sm;                    // CIN*PH*PWP
    float* sW  = sm + CIN*PH*PWP;       // COB*CIN*9

    const int b     = blockIdx.z;
    const int co0   = blockIdx.y * COB;
    const int tileX = (blockIdx.x % tilesX) * TILEW;
    const int tileY = (blockIdx.x / tilesX) * TY;
    const int tid   = threadIdx.x;

    const int iy0 = tileY*S - 1, ix0 = tileX*S - 1;
    const float* inb = in + (long)b*CIN*HIN*WIN;

    // Batched input staging: 8 independent LDGs in flight per round.
    #pragma unroll 1
    for (int bb = 0; bb < NB; bb++) {
        float v[8];
        #pragma unroll
        for (int j = 0; j < 8; j++) {
            int i = (bb*8 + j)*NT + tid;
            v[j] = 0.0f;
            if (i < TOT) {
                int ci = i / (PH*PW); int rem = i - ci*(PH*PW);
                int r = rem / PW;     int c = rem - r*PW;
                int iy = iy0 + r, ix = ix0 + c;
                if ((unsigned)iy < (unsigned)HIN && (unsigned)ix < (unsigned)WIN)
                    v[j] = __ldg(&inb[(ci*HIN + iy)*WIN + ix]);
            }
        }
        #pragma unroll
        for (int j = 0; j < 8; j++) {
            int i = (bb*8 + j)*NT + tid;
            if (i < TOT) {
                int ci = i / (PH*PW); int rem = i - ci*(PH*PW);
                int r = rem / PW;     int c = rem - r*PW;
                sIn[(ci*PH + r)*PWP + c] = v[j];
            }
        }
    }
    // Weights (contiguous chunk for this co block)
    for (int i = tid; i < WTOT; i += NT)
        sW[i] = __ldg(&wt[(long)co0*CIN*9 + i]);
    __syncthreads();

    const int y  = tid % TY;
    const int cg = (tid / TY) % CG;
    const int xg = tid / (TY*CG);

    float acc[CPT][TX];
    #pragma unroll
    for (int c = 0; c < CPT; c++)
        #pragma unroll
        for (int x = 0; x < TX; x++) acc[c][x] = 0.0f;

    #pragma unroll 1
    for (int ci = 0; ci < CIN; ci++) {
        float w[CPT][9];
        #pragma unroll
        for (int c = 0; c < CPT; c++)
            #pragma unroll
            for (int k = 0; k < 9; k++)
                w[c][k] = sW[(cg*CPT + c)*CIN*9 + ci*9 + k];
        #pragma unroll
        for (int ky = 0; ky < 3; ky++) {
            const float* rp = &sIn[(ci*PH + y*S + ky)*PWP + xg*TX*S];
            float row[WR];
            #pragma unroll
            for (int j = 0; j < WR; j++) row[j] = rp[j];
            #pragma unroll
            for (int x = 0; x < TX; x++)
                #pragma unroll
                for (int kx = 0; kx < 3; kx++)
                    #pragma unroll
                    for (int c = 0; c < CPT; c++)
                        acc[c][x] = fmaf(row[x*S + kx], w[c][ky*3 + kx], acc[c][x]);
        }
    }

    #pragma unroll
    for (int c = 0; c < CPT; c++) {
        int co = co0 + cg*CPT + c;
        float bv = HB ? bias[co] : 0.0f;
        #pragma unroll
        for (int x = 0; x < TX; x++) {
            float v = acc[c][x] + bv;
            if (RELU) v = relu_(v);
            out[((b*Cout + co)*HOUT + tileY + y)*WOUT + tileX + xg*TX + x] = v;
        }
    }
}

// ---------------------------------------------------------------------------
// s0: in = concat(nearest(lqs,256), evs) [8,18,256,256] -> conv3x3 s2 p1 relu
//     -> [8,8,128,128]. Batched gathered staging, 256 thr, 512 blocks.
// ---------------------------------------------------------------------------
__global__ void s0f_kernel(const float* __restrict__ lqs, const float* __restrict__ evs,
                           const float* __restrict__ wt,  const float* __restrict__ bias,
                           float* __restrict__ out)
{
    constexpr int PH = 33, PW = 33, PWP = 33, NT = 256;
    constexpr int TOT = 18*PH*PW;                 // 19602
    constexpr int NB  = (TOT + NT*8 - 1)/(NT*8);  // 10
    extern __shared__ float sm[];
    float* sIn = sm;                 // 18*33*33
    float* sW  = sm + 18*PH*PWP;     // 8*18*9

    const int b     = blockIdx.z;
    const int tileX = (blockIdx.x % 8) * 16;
    const int tileY = (blockIdx.x / 8) * 16;
    const int tid   = threadIdx.x;

    const int iy0 = tileY*2 - 1, ix0 = tileX*2 - 1;

    #pragma unroll 1
    for (int bb = 0; bb < NB; bb++) {
        float v[8];
        #pragma unroll
        for (int j = 0; j < 8; j++) {
            int i = (bb*8 + j)*NT + tid;
            v[j] = 0.0f;
            if (i < TOT) {
                int ci = i / (PH*PW); int rem = i - ci*(PH*PW);
                int r = rem / PW;     int c = rem - r*PW;
                int iy = iy0 + r, ix = ix0 + c;
                if ((unsigned)iy < 256u && (unsigned)ix < 256u) {
                    if (ci < 3) v[j] = __ldg(&lqs[(b*3 + ci)*1048576 + iy*4096 + ix*4]);
                    else        v[j] = __ldg(&evs[(b*15 + (ci-3))*65536 + iy*256 + ix]);
                }
            }
        }
        #pragma unroll
        for (int j = 0; j < 8; j++) {
            int i = (bb*8 + j)*NT + tid;
            if (i < TOT) {
                int ci = i / (PH*PW); int rem = i - ci*(PH*PW);
                int r = rem / PW;     int c = rem - r*PW;
                sIn[(ci*PH + r)*PWP + c] = v[j];
            }
        }
    }
    for (int i = tid; i < 8*18*9; i += NT) sW[i] = __ldg(&wt[i]);
    __syncthreads();

    const int y  = tid % 16;
    const int cg = (tid / 16) % 8;   // co (1 each)
    const int xg = tid / 128;        // 0..1

    float acc[8];
    #pragma unroll
    for (int x = 0; x < 8; x++) acc[x] = 0.0f;

    #pragma unroll 1
    for (int ci = 0; ci < 18; ci++) {
        float w[9];
        #pragma unroll
        for (int k = 0; k < 9; k++) w[k] = sW[(cg*18 + ci)*9 + k];
        #pragma unroll
        for (int ky = 0; ky < 3; ky++) {
            const float* rp = &sIn[(ci*PH + y*2 + ky)*PWP + xg*16];
            float row[17];
            #pragma unroll
            for (int j = 0; j < 17; j++) row[j] = rp[j];
            #pragma unroll
            for (int x = 0; x < 8; x++)
                #pragma unroll
                for (int kx = 0; kx < 3; kx++)
                    acc[x] = fmaf(row[x*2 + kx], w[ky*3 + kx], acc[x]);
        }
    }

    float bv = bias[cg];
    #pragma unroll
    for (int x = 0; x < 8; x++)
        out[((b*8 + cg)*128 + tileY + y)*128 + tileX + xg*8 + x] = relu_(acc[x] + bv);
}

// ---------------------------------------------------------------------------
// Fused cw1 (conv3x3 s2: [64,8,8]->[64,4,4]) + FC 1024->256->128->64.
// One block per batch, 256 threads. FC dots warp-per-output, coalesced.
// ---------------------------------------------------------------------------
__global__ void cw1fc_kernel(const float* __restrict__ c0,
                             const float* __restrict__ cw1, const float* __restrict__ cb1,
                             const float* __restrict__ fw1, const float* __restrict__ fb1,
                             const float* __restrict__ fw2, const float* __restrict__ fb2,
                             const float* __restrict__ fw3, const float* __restrict__ fb3,
                             float* __restrict__ xg)
{
    extern __shared__ float sm[];
    float* sC  = sm;             // 64*10*11 = 7040
    float* sWt = sC + 7040;      // 36864
    float* sc1 = sWt + 36864;    // 1024
    float* s1f = sc1 + 1024;     // 256
    float* s2f = s1f + 256;      // 128

    const int b = blockIdx.x, tid = threadIdx.x;   // 256 threads

    for (int i = tid; i < 64*10*10; i += 256) {
        int ci = i / 100; int rem = i - ci*100;
        int r = rem / 10, c = rem - (rem/10)*10;
        int iy = r - 1, ix = c - 1;
        float v = 0.0f;
        if ((unsigned)iy < 8u && (unsigned)ix < 8u)
            v = c0[((b*64 + ci)*8 + iy)*8 + ix];
        sC[(ci*10 + r)*11 + c] = v;
    }
    for (int i = tid; i < 36864; i += 256) sWt[i] = cw1[i];
    __syncthreads();

    {
        int co = tid >> 2, y = tid & 3;
        float acc[4] = {0.0f, 0.0f, 0.0f, 0.0f};
        #pragma unroll 1
        for (int ci = 0; ci < 64; ci++) {
            float w[9];
            #pragma unroll
            for (int k = 0; k < 9; k++) w[k] = sWt[(co*64 + ci)*9 + k];
            #pragma unroll
            for (int ky = 0; ky < 3; ky++) {
                const float* rp = &sC[(ci*10 + y*2 + ky)*11];
                float row[9];
                #pragma unroll
                for (int j = 0; j < 9; j++) row[j] = rp[j];
                #pragma unroll
                for (int x = 0; x < 4; x++)
                    #pragma unroll
                    for (int kx = 0; kx < 3; kx++)
                        acc[x] = fmaf(row[x*2 + kx], w[ky*3 + kx], acc[x]);
            }
        }
        float bv = cb1[co];
        #pragma unroll
        for (int x = 0; x < 4; x++)
            sc1[co*16 + y*4 + x] = relu_(acc[x] + bv);
    }
    __syncthreads();

    const int lane = tid & 31, wp = tid >> 5;    // 8 warps

    for (int j = 0; j < 32; j++) {
        int o = wp*32 + j;
        const float* wr = fw1 + o*1024;
        float a = 0.0f;
        #pragma unroll 4
        for (int k = lane; k < 1024; k += 32) a = fmaf(wr[k], sc1[k], a);
        a = warp_sum(a);
        if (lane == 0) s1f[o] = relu_(a + fb1[o]);
    }
    __syncthreads();

    for (int j = 0; j < 16; j++) {
        int o = wp*16 + j;
        const float* wr = fw2 + o*256;
        float a = 0.0f;
        #pragma unroll
        for (int k = lane; k < 256; k += 32) a = fmaf(wr[k], s1f[k], a);
        a = warp_sum(a);
        if (lane == 0) s2f[o] = relu_(a + fb2[o]);
    }
    __syncthreads();

    for (int j = 0; j < 8; j++) {
        int o = wp*8 + j;
        const float* wr = fw3 + o*128;
        float a = 0.0f;
        #pragma unroll
        for (int k = lane; k < 128; k += 32) a = fmaf(wr[k], s2f[k], a);
        a = warp_sum(a);
        if (lane == 0) xg[b*64 + o] = a + fb3[o];
    }
}

// ---------------------------------------------------------------------------
// bg = conv1x1(relu(xg[b,c] + xl[b,c,y,x]), fuw) + fub  -> [B,8,16,16]
// ---------------------------------------------------------------------------
__global__ void bg_kernel(const float* __restrict__ xl, const float* __restrict__ xg,
                          const float* __restrict__ fuw, const float* __restrict__ fub,
                          float* __restrict__ bg)
{
    int b = blockIdx.x, p = threadIdx.x;   // 256 threads = 16x16 pixels
    __shared__ float sxg[64];
    __shared__ float sw[8*64];
    if (p < 64) sxg[p] = xg[b*64 + p];
    for (int i = p; i < 512; i += 256) sw[i] = fuw[i];
    __syncthreads();
    float acc[8];
    #pragma unroll
    for (int g = 0; g < 8; g++) acc[g] = fub[g];
    for (int c = 0; c < 64; c++) {
        float f = relu_(sxg[c] + xl[(b*64 + c)*256 + p]);
        #pragma unroll
        for (int g = 0; g < 8; g++) acc[g] = fmaf(sw[g*64 + c], f, acc[g]);
    }
    #pragma unroll
    for (int g = 0; g < 8; g++) bg[(b*8 + g)*256 + p] = acc[g];
}

// ---------------------------------------------------------------------------
// guide_kernel: Gaussian blur (separable, reflect) + 1x1 convs -> guide map.
// ---------------------------------------------------------------------------
__device__ __forceinline__ int reflect1024(int i) {
    return i < 0 ? -i : (i > 1023 ? 2046 - i : i);
}

__global__ __launch_bounds__(256, 2)
void guide_kernel(const float* __restrict__ lqs,
                  const float* __restrict__ gw1, const float* __restrict__ gb1,
                  const float* __restrict__ gw2, const float* __restrict__ gb2,
                  float* __restrict__ guide)
{
    __shared__ float sIn[3][48][49];
    __shared__ float sMid[3][48][33];
    __shared__ float sW[81];

    const int tid = threadIdx.x;
    const int bx = blockIdx.x*32, by = blockIdx.y*32, b = blockIdx.z;

    if (tid < 81)
        sW[tid] = (tid < 48) ? gw1[tid]
                : (tid < 64) ? gb1[tid - 48]
                : (tid < 80) ? gw2[tid - 64] : gb2[0];

    const float* base = lqs + b*3*1048576;

    for (int i = tid; i < 3*48*48; i += 256) {
        int ch = i / 2304; int rem = i - ch*2304;
        int r = rem / 48;  int c  = rem - r*48;
        sIn[ch][r][c] = base[ch*1048576 + reflect1024(by + r - 8)*1024 + reflect1024(bx + c - 8)];
    }
    __syncthreads();

    for (int s = tid; s < 288; s += 256) {
        int ch = s / 96; int rem = s - ch*96;
        int r = rem >> 1; int half = rem & 1;
        int c0 = half * 16;
        float w[32];
        #pragma unroll
        for (int j = 0; j < 32; j++) w[j] = sIn[ch][r][c0 + j];
        #pragma unroll
        for (int o = 0; o < 16; o++) {
            float a = 0.0f;
            #pragma unroll
            for (int k = 0; k < 17; k++) a = fmaf(GW[k], w[o + k], a);
            sMid[ch][r][c0 + o] = a;
        }
    }
    __syncthreads();

    const int tx = tid & 31;
    const int qy = tid >> 5;
    float vb[3][4];
    #pragma unroll
    for (int ch = 0; ch < 3; ch++) {
        float col[20];
        #pragma unroll
        for (int k = 0; k < 20; k++) col[k] = sMid[ch][qy*4 + k][tx];
        #pragma unroll
        for (int d = 0; d < 4; d++) {
            float a = 0.0f;
            #pragma unroll
            for (int k = 0; k < 17; k++) a = fmaf(GW[k], col[d + k], a);
            vb[ch][d] = a;
        }
    }

    const int ox = bx + tx;
    #pragma unroll
    for (int d = 0; d < 4; d++) {
        float ssum = sW[80];
        #pragma unroll
        for (int o = 0; o < 16; o++) {
            float h = fmaf(sW[o*3], vb[0][d], fmaf(sW[o*3+1], vb[1][d], fmaf(sW[o*3+2], vb[2][d], sW[48+o])));
            h = relu_(h);
            ssum = fmaf(sW[64+o], h, ssum);
        }
        float sig = 1.0f / (1.0f + __expf(-ssum));
        int oy = by + qy*4 + d;
        guide[b*1048576 + oy*1024 + ox] = 2.0f*sig - 0.5f;
    }
}

// ---------------------------------------------------------------------------
// slice_kernel: trilinear slice of bilateral grid using guide map. float4 I/O.
// ---------------------------------------------------------------------------
__global__ void slice_kernel(const float* __restrict__ guide,
                             const float* __restrict__ bg, float* __restrict__ out)
{
    int idx = blockIdx.x*256 + threadIdx.x;     // 2,097,152 threads (x4 px)
    int b   = idx >> 18;
    int rem = idx & 0x3FFFF;
    int py  = rem >> 8;
    int px0 = (rem & 255) << 2;

    float4 g4 = ((const float4*)guide)[idx];
    float gv[4] = {g4.x, g4.y, g4.z, g4.w};

    float gyv = (py + 0.5f) * (1.0f/1024.0f) * 2.0f - 0.5f;
    float ys  = fminf(fmaxf(((gyv + 1.0f)*16.0f - 1.0f)*0.5f, 0.0f), 15.0f);
    float y0f = floorf(ys);
    int   y0  = (int)y0f;
    float fy  = ys - y0f;
    int   y1  = min(y0 + 1, 15);

    const float* bgb = bg + b*2048;
    float res[4];
    #pragma unroll
    for (int j = 0; j < 4; j++) {
        int px = px0 + j;
        float gxv = (px + 0.5f) * (1.0f/1024.0f) * 2.0f - 0.5f;
        float xs  = fminf(fmaxf(((gxv + 1.0f)*16.0f - 1.0f)*0.5f, 0.0f), 15.0f);
        float x0f = floorf(xs);
        int   x0  = (int)x0f;
        float fx  = xs - x0f;
        int   x1  = min(x0 + 1, 15);

        float zs  = fminf(fmaxf(((gv[j] + 1.0f)*8.0f - 1.0f)*0.5f, 0.0f), 7.0f);
        float z0f = floorf(zs);
        int   z0  = (int)z0f;
        float fz  = zs - z0f;
        int   z1  = min(z0 + 1, 7);

        float v000 = __ldg(&bgb[z0*256 + y0*16 + x0]);
        float v001 = __ldg(&bgb[z0*256 + y0*16 + x1]);
        float v010 = __ldg(&bgb[z0*256 + y1*16 + x0]);
        float v011 = __ldg(&bgb[z0*256 + y1*16 + x1]);
        float v100 = __ldg(&bgb[z1*256 + y0*16 + x0]);
        float v101 = __ldg(&bgb[z1*256 + y0*16 + x1]);
        float v110 = __ldg(&bgb[z1*256 + y1*16 + x0]);
        float v111 = __ldg(&bgb[z1*256 + y1*16 + x1]);

        float c00 = v000 + (v001 - v000)*fx;
        float c01 = v010 + (v011 - v010)*fx;
        float c10 = v100 + (v101 - v100)*fx;
        float c11 = v110 + (v111 - v110)*fx;
        float c0v = c00 + (c01 - c00)*fy;
        float c1v = c10 + (c11 - c10)*fy;
        res[j] = c0v + (c1v - c0v)*fz;
    }
    ((float4*)out)[idx] = make_float4(res[0], res[1], res[2], res[3]);
}

// ---------------------------------------------------------------------------
// kernel_launch
// ---------------------------------------------------------------------------
extern "C" void kernel_launch(void* const* d_in, const int* in_sizes, int n_in,
                              void* d_out, int out_size)
{
    const float* lqs = (const float*)d_in[0];
    const float* evs = (const float*)d_in[1];
    const float* gw1 = (const float*)d_in[2];
    const float* gb1 = (const float*)d_in[3];
    const float* gw2 = (const float*)d_in[4];
    const float* gb2 = (const float*)d_in[5];
    const float* sw0 = (const float*)d_in[6];
    const float* sb0 = (const float*)d_in[7];
    const float* sw1 = (const float*)d_in[8];
    const float* sb1 = (const float*)d_in[9];
    const float* sw2 = (const float*)d_in[10];
    const float* sb2 = (const float*)d_in[11];
    const float* sw3 = (const float*)d_in[12];
    const float* sb3 = (const float*)d_in[13];
    const float* cw0 = (const float*)d_in[14];
    const float* cb0 = (const float*)d_in[15];
    const float* cw1 = (const float*)d_in[16];
    const float* cb1 = (const float*)d_in[17];
    const float* fw1 = (const float*)d_in[18];
    const float* fb1 = (const float*)d_in[19];
    const float* fw2 = (const float*)d_in[20];
    const float* fb2 = (const float*)d_in[21];
    const float* fw3 = (const float*)d_in[22];
    const float* fb3 = (const float*)d_in[23];
    const float* lw1 = (const float*)d_in[24];
    const float* lb1 = (const float*)d_in[25];
    const float* lw2 = (const float*)d_in[26];
    const float* fuw = (const float*)d_in[27];
    const float* fub = (const float*)d_in[28];
    float* out = (float*)d_out;

    float *ps0, *ps1, *ps2, *ps3, *pl1, *pxl, *pc0, *pxg, *pbg, *pgd;
    cudaGetSymbolAddress((void**)&ps0, g_s0);
    cudaGetSymbolAddress((void**)&ps1, g_s1);
    cudaGetSymbolAddress((void**)&ps2, g_s2);
    cudaGetSymbolAddress((void**)&ps3, g_s3);
    cudaGetSymbolAddress((void**)&pl1, g_l1);
    cudaGetSymbolAddress((void**)&pxl, g_xl);
    cudaGetSymbolAddress((void**)&pc0, g_c0);
    cudaGetSymbolAddress((void**)&pxg, g_xg);
    cudaGetSymbolAddress((void**)&pbg, g_bg);
    cudaGetSymbolAddress((void**)&pgd, g_guide);

    // Dynamic smem sizes (bytes)
    const int SM_S0  = (18*33*33 + 8*18*9)  * 4;   //  83592
    const int SM_S1  = (8*33*33  + 16*8*9)  * 4;   //  39456
    const int SM_S2  = (16*33*33 + 16*16*9) * 4;   //  78912
    const int SM_S3  = (32*33*33 + 16*32*9) * 4;   // 157824
    const int SM_LW  = (64*18*19 + 8*64*9)  * 4;   // 105984
    const int SM_CW0 = (64*17*17 + 32*64*9) * 4;   // 147712
    const int SM_FC  = (7040 + 36864 + 1024 + 256 + 128) * 4;  // 181248

    // Lazy one-time side streams + events + func attrs (created on the
    // uncaptured correctness call; reused identically afterwards).
    static cudaStream_t s_side = nullptr, s_cw = nullptr;
    static cudaEvent_t  ev_fork = nullptr, ev_join = nullptr, ev_s3 = nullptr, ev_cw = nullptr;
    if (!s_side) {
        cudaStreamCreateWithFlags(&s_side, cudaStreamNonBlocking);
        cudaStreamCreateWithFlags(&s_cw,   cudaStreamNonBlocking);
        cudaEventCreateWithFlags(&ev_fork, cudaEventDisableTiming);
        cudaEventCreateWithFlags(&ev_join, cudaEventDisableTiming);
        cudaEventCreateWithFlags(&ev_s3,   cudaEventDisableTiming);
        cudaEventCreateWithFlags(&ev_cw,   cudaEventDisableTiming);
        cudaFuncSetAttribute(s0f_kernel, cudaFuncAttributeMaxDynamicSharedMemorySize, SM_S0);
        cudaFuncSetAttribute(convf3_kernel<16,2,16,2,16,8,2,true,true>,  cudaFuncAttributeMaxDynamicSharedMemorySize, SM_S2);
        cudaFuncSetAttribute(convf3_kernel<32,2,16,2,16,8,2,true,true>,  cudaFuncAttributeMaxDynamicSharedMemorySize, SM_S3);
        cudaFuncSetAttribute(convf3_kernel<64,1,8,1,16,8,2,true,true>,   cudaFuncAttributeMaxDynamicSharedMemorySize, SM_LW);
        cudaFuncSetAttribute(convf3_kernel<64,1,8,1,16,8,2,false,false>, cudaFuncAttributeMaxDynamicSharedMemorySize, SM_LW);
        cudaFuncSetAttribute(convf3_kernel<64,2,32,1,8,8,1,true,true>,   cudaFuncAttributeMaxDynamicSharedMemorySize, SM_CW0);
        cudaFuncSetAttribute(cw1fc_kernel, cudaFuncAttributeMaxDynamicSharedMemorySize, SM_FC);
    }

    // ---- fork: guide path runs concurrent with the lowres chain ----
    cudaEventRecord(ev_fork, 0);
    cudaStreamWaitEvent(s_side, ev_fork, 0);
    guide_kernel<<<dim3(32, 32, 8), 256, 0, s_side>>>(lqs, gw1, gb1, gw2, gb2, pgd);

    // ---- lowres trunk (batched-staging convf3) ----
    s0f_kernel<<<dim3(64, 1, 8), 256, SM_S0>>>(lqs, evs, sw0, sb0, ps0);
    convf3_kernel<8,2,16,2,16,8,2,true,true>
        <<<dim3(16, 1, 8), 256, SM_S1>>>(ps0, sw1, sb1, ps1, 128, 128, 16, 64, 64, 4);
    convf3_kernel<16,2,16,2,16,8,2,true,true>
        <<<dim3(4, 2, 8), 256, SM_S2>>>(ps1, sw2, sb2, ps2, 64, 64, 32, 32, 32, 2);
    convf3_kernel<32,2,16,2,16,8,2,true,true>
        <<<dim3(1, 4, 8), 256, SM_S3>>>(ps2, sw3, sb3, ps3, 32, 32, 64, 16, 16, 1);

    // ---- fork global head (cw0 -> cw1fc) onto s_cw, local head on main ----
    cudaEventRecord(ev_s3, 0);
    cudaStreamWaitEvent(s_cw, ev_s3, 0);
    convf3_kernel<64,2,32,1,8,8,1,true,true>
        <<<dim3(1, 2, 8), 256, SM_CW0, s_cw>>>(ps3, cw0, cb0, pc0, 16, 16, 64, 8, 8, 1);
    cw1fc_kernel<<<8, 256, SM_FC, s_cw>>>(pc0, cw1, cb1, fw1, fb1, fw2, fb2, fw3, fb3, pxg);
    cudaEventRecord(ev_cw, s_cw);

    convf3_kernel<64,1,8,1,16,8,2,true,true>
        <<<dim3(1, 8, 8), 256, SM_LW>>>(ps3, lw1, lb1, pl1, 16, 16, 64, 16, 16, 1);
    convf3_kernel<64,1,8,1,16,8,2,false,false>
        <<<dim3(1, 8, 8), 256, SM_LW>>>(pl1, lw2, (const float*)nullptr, pxl, 16, 16, 64, 16, 16, 1);

    // ---- join heads, build bilateral grid ----
    cudaStreamWaitEvent(0, ev_cw, 0);
    bg_kernel<<<8, 256>>>(pxl, pxg, fuw, fub, pbg);

    // ---- join guide, slice ----
    cudaEventRecord(ev_join, s_side);
    cudaStreamWaitEvent(0, ev_join, 0);
    slice_kernel<<<8192, 256>>>(pgd, pbg, out);
}